// round 7
// baseline (speedup 1.0000x reference)
#include <cuda_runtime.h>
#include <math.h>

// Problem constants
#define BB 128
#define NN 2000
#define CC 100
#define DD 128
#define HH 8
#define DKK 16
#define NEGV (-1000000000.0f)
#define CLIPV 10.0f

// Output layout (float32, flattened tuple order)
// aug:      [0,        65536)   B*512
// guid_emb: [65536,    81920)   B*128
// guidance: [81920,    82048)   B
// clu_prob: [82048,    94848)   B*100
#define OUT_AUG 0
#define OUT_GEMB 65536
#define OUT_GUID 81920
#define OUT_CLU 82048

// Shared memory layout (float offsets). All float4 regions are 16B aligned.
#define S_CS 0           // cluster tile [100][129]
#define S_WB 12900       // weight stage / reduction scratch [128][129]
#define S_M1 29412       // mean1 [128]
#define S_M2 29540       // mean2 [128]
#define S_CUR 29668      // current [128]
#define S_DEP 29796      // depot [128]
#define S_CTX 29924      // context [384]
#define S_QV 30308       // q [128]
#define S_QH 30436       // qh [128]
#define S_R4 30564       // r packed [128][8]
#define S_U4 31588       // u packed [128][8]
#define S_SC 32612       // scores [8][104]
#define S_AT4 33444      // attn packed [100][8]
#define S_WS4 34244      // wsum packed [128][8]
#define S_YS 35268       // y [8][132]
#define S_GV 36324       // glimpse (pre-Wmo) [128]
#define S_GO 36452       // glimpse @ Wmo [128]
#define S_GW 36580       // Wks @ go [128]
#define S_PART 36708     // logit partials [100][2] (pad 208)
#define S_LGT 36916      // logits [104]
#define S_MISC 37020     // [0]=gid [1]=max+lse
#define S_VCM 37036      // vcm [104]
#define SMEM_FLOATS 37140
#define SMEM_BYTES (SMEM_FLOATS * 4)

__device__ __forceinline__ bool rdmask(const void* p, int flag, long long i) {
    if (flag == 0) return ((const unsigned char*)p)[i] != 0;
    if (flag == 1) return ((const int*)p)[i] != 0;
    return ((const float*)p)[i] != 0.0f;
}

// Masked-mean accumulation over node_embeddings, specialized on mask dtype.
template <int F>
__device__ __forceinline__ void means_acc(const float* __restrict__ np_,
                                          const void* __restrict__ maskp,
                                          const void* __restrict__ cmaskp,
                                          long long mbase, int w, int d0,
                                          float4& a1, float4& a2) {
#pragma unroll 5
    for (int n = w; n < NN; n += 8) {
        float4 v = *(const float4*)(np_ + (size_t)n * DD + d0);
        bool m, cmv;
        if (F == 0) {
            m = ((const unsigned char*)maskp)[mbase + n] != 0;
            cmv = ((const unsigned char*)cmaskp)[mbase + n] != 0;
        } else if (F == 1) {
            m = ((const int*)maskp)[mbase + n] != 0;
            cmv = ((const int*)cmaskp)[mbase + n] != 0;
        } else {
            m = ((const float*)maskp)[mbase + n] != 0.0f;
            cmv = ((const float*)cmaskp)[mbase + n] != 0.0f;
        }
        bool mc = m | cmv;
        if (!m)  { a1.x += v.x; a1.y += v.y; a1.z += v.z; a1.w += v.w; }
        if (!mc) { a2.x += v.x; a2.y += v.y; a2.z += v.z; a2.w += v.w; }
    }
}

__global__ void __launch_bounds__(256, 1)
clu_fused_kernel(const float* __restrict__ depot, const float* __restrict__ cluster,
                 const float* __restrict__ curE, const float* __restrict__ node,
                 const void* __restrict__ isnewp, const void* __restrict__ cmaskp,
                 const void* __restrict__ vcmp, const void* __restrict__ maskp,
                 const float* __restrict__ Wq, const float* __restrict__ Wk,
                 const float* __restrict__ Wv, const float* __restrict__ Wks,
                 const float* __restrict__ Wmq, const float* __restrict__ Wmk,
                 const float* __restrict__ Wmv, const float* __restrict__ Wmo,
                 float* __restrict__ out) {
    extern __shared__ float sm[];
    const int b = blockIdx.x;
    const int t = threadIdx.x;
    const int lane = t & 31;
    const int w = t >> 5;

    // ---- Phase 0a: sniff bool serialization dtype (byte / int32 / float32) ----
    unsigned wword = ((const unsigned*)maskp)[t];  // first 1024 bytes of `mask`
    int o1  = __syncthreads_or((wword & 0x0000ff00u) ? 1 : 0);
    int o23 = __syncthreads_or((wword & 0xffff0000u) ? 1 : 0);
    const int flag = o1 ? 0 : (o23 ? 2 : 1);

    // ---- Phase 0b: small loads (current/depot/vcm), cluster tile -> smem ----
    if (t < DD) {
        sm[S_CUR + t] = curE[b * DD + t];
        sm[S_DEP + t] = depot[b * DD + t];
    }
    if (t < CC) sm[S_VCM + t] = rdmask(vcmp, flag, (long long)b * CC + t) ? 1.0f : 0.0f;
    const bool isnew = rdmask(isnewp, flag, b);

    {
        const float* cp = cluster + (size_t)b * CC * DD;
        for (int p4 = t; p4 < (CC * DD) / 4; p4 += 256) {
            float4 v = ((const float4*)cp)[p4];
            int base = p4 * 4;
            float* dst = sm + S_CS + (base >> 7) * 129 + (base & 127);
            dst[0] = v.x; dst[1] = v.y; dst[2] = v.z; dst[3] = v.w;
        }
    }
    __syncthreads();

    // vcm[0] adjustment: all_vis over c=1..99 (warp 0)
    if (w == 0) {
        bool ok = true;
        for (int c = 1 + lane; c < CC; c += 32) ok = ok && (sm[S_VCM + c] != 0.0f);
        bool allv = __all_sync(0xffffffffu, ok);
        if (lane == 0 && isnew) sm[S_VCM + 0] = allv ? 0.0f : 1.0f;
    }

    // ---- Phase 1: masked means over node_embeddings (the HBM pass) ----
    {
        const float* np_ = node + (size_t)b * NN * DD;
        const long long mbase = (long long)b * NN;
        const int d0 = lane * 4;
        float4 a1 = make_float4(0.f, 0.f, 0.f, 0.f);
        float4 a2 = make_float4(0.f, 0.f, 0.f, 0.f);
        if (flag == 0)      means_acc<0>(np_, maskp, cmaskp, mbase, w, d0, a1, a2);
        else if (flag == 1) means_acc<1>(np_, maskp, cmaskp, mbase, w, d0, a1, a2);
        else                means_acc<2>(np_, maskp, cmaskp, mbase, w, d0, a1, a2);
        // deterministic cross-warp reduction via Wb scratch
        float* red1 = sm + S_WB;
        float* red2 = sm + S_WB + 1024;
        int o = w * 128 + d0;
        red1[o] = a1.x; red1[o + 1] = a1.y; red1[o + 2] = a1.z; red1[o + 3] = a1.w;
        red2[o] = a2.x; red2[o + 1] = a2.y; red2[o + 2] = a2.z; red2[o + 3] = a2.w;
    }
    __syncthreads();
    if (t < DD) {
        float s1 = 0.f, s2 = 0.f;
#pragma unroll
        for (int ww = 0; ww < 8; ww++) {
            s1 += sm[S_WB + ww * 128 + t];
            s2 += sm[S_WB + 1024 + ww * 128 + t];
        }
        float m1 = s1 * (1.0f / NN), m2 = s2 * (1.0f / NN);
        sm[S_M1 + t] = m1;
        sm[S_M2 + t] = m2;
        sm[S_CTX + t] = m1;
        sm[S_CTX + 128 + t] = sm[S_CUR + t];
        sm[S_CTX + 256 + t] = sm[S_DEP + t];
    }
    __syncthreads();

    // ---- Phase 2: q = ctx @ Wq ; qh = q @ Wmq ----
    if (t < DD) {
        float acc = 0.f;
#pragma unroll 8
        for (int i = 0; i < 3 * DD; i++) acc = fmaf(sm[S_CTX + i], Wq[i * DD + t], acc);
        sm[S_QV + t] = acc;
    }
    __syncthreads();
    if (t < DD) {
        float acc = 0.f;
#pragma unroll 8
        for (int j = 0; j < DD; j++) acc = fmaf(sm[S_QV + j], Wmq[j * DD + t], acc);
        sm[S_QH + t] = acc;
    }
    __syncthreads();

    // ---- Phase 3: stage Wmk; r[h][j] = sum_k Wmk[j][16h+k]*qh[16h+k] ----
    for (int p4 = t; p4 < (DD * DD) / 4; p4 += 256) {
        float4 v = ((const float4*)Wmk)[p4];
        int base = p4 * 4;
        float* dst = sm + S_WB + (base >> 7) * 129 + (base & 127);
        dst[0] = v.x; dst[1] = v.y; dst[2] = v.z; dst[3] = v.w;
    }
    __syncthreads();
    {
        int j = t & 127, par = t >> 7;
        float racc[4];
#pragma unroll
        for (int m = 0; m < 4; m++) {
            int h = par + 2 * m;
            float a = 0.f;
#pragma unroll
            for (int k = 0; k < 16; k++)
                a = fmaf(sm[S_WB + j * 129 + 16 * h + k], sm[S_QH + 16 * h + k], a);
            racc[m] = a;
        }
        float* dst = sm + S_R4 + j * 8 + par * 4;
        dst[0] = racc[0]; dst[1] = racc[1]; dst[2] = racc[2]; dst[3] = racc[3];
    }
    __syncthreads();

    // ---- Phase 4: stage Wk; u[h][i] = sum_j Wk[i][j]*r[h][j] ----
    for (int p4 = t; p4 < (DD * DD) / 4; p4 += 256) {
        float4 v = ((const float4*)Wk)[p4];
        int base = p4 * 4;
        float* dst = sm + S_WB + (base >> 7) * 129 + (base & 127);
        dst[0] = v.x; dst[1] = v.y; dst[2] = v.z; dst[3] = v.w;
    }
    __syncthreads();
    {
        int i = t & 127, par = t >> 7;
        float acc[4] = {0.f, 0.f, 0.f, 0.f};
#pragma unroll 4
        for (int j = 0; j < DD; j++) {
            float wv_ = sm[S_WB + i * 129 + j];
            float4 rv = *(const float4*)(sm + S_R4 + j * 8 + par * 4);
            acc[0] = fmaf(wv_, rv.x, acc[0]);
            acc[1] = fmaf(wv_, rv.y, acc[1]);
            acc[2] = fmaf(wv_, rv.z, acc[2]);
            acc[3] = fmaf(wv_, rv.w, acc[3]);
        }
        float* dst = sm + S_U4 + i * 8 + par * 4;
        dst[0] = acc[0]; dst[1] = acc[1]; dst[2] = acc[2]; dst[3] = acc[3];
    }
    __syncthreads();

    // ---- Phase 5: scores[c][h] = cluster[c]·u[h] * 0.25, masked ----
    if (t < 2 * CC) {
        int c = t >> 1, par = t & 1;
        float acc[4] = {0.f, 0.f, 0.f, 0.f};
#pragma unroll 4
        for (int i = 0; i < DD; i++) {
            float cv = sm[S_CS + c * 129 + i];
            float4 uu = *(const float4*)(sm + S_U4 + i * 8 + par * 4);
            acc[0] = fmaf(cv, uu.x, acc[0]);
            acc[1] = fmaf(cv, uu.y, acc[1]);
            acc[2] = fmaf(cv, uu.z, acc[2]);
            acc[3] = fmaf(cv, uu.w, acc[3]);
        }
        bool msk = sm[S_VCM + c] != 0.0f;
#pragma unroll
        for (int m = 0; m < 4; m++) {
            int h = par + 2 * m;
            sm[S_SC + h * 104 + c] = msk ? NEGV : acc[m] * 0.25f;
        }
    }
    __syncthreads();

    // ---- Phase 5b: softmax over c, per head (warp h) ----
    {
        int h = w;
        float mx = -INFINITY;
        for (int c = lane; c < CC; c += 32) mx = fmaxf(mx, sm[S_SC + h * 104 + c]);
#pragma unroll
        for (int off = 16; off; off >>= 1) mx = fmaxf(mx, __shfl_xor_sync(0xffffffffu, mx, off));
        float s = 0.f;
        for (int c = lane; c < CC; c += 32) {
            float e = expf(sm[S_SC + h * 104 + c] - mx);
            s += e;
            sm[S_AT4 + c * 8 + (h & 1) * 4 + (h >> 1)] = e;
        }
#pragma unroll
        for (int off = 16; off; off >>= 1) s += __shfl_xor_sync(0xffffffffu, s, off);
        float inv = 1.0f / s;
        for (int c = lane; c < CC; c += 32)
            sm[S_AT4 + c * 8 + (h & 1) * 4 + (h >> 1)] *= inv;
    }
    __syncthreads();

    // ---- Phase 6: wsum[h][i] = sum_c attn[h][c]*cluster[c][i] ----
    {
        int i = t & 127, par = t >> 7;
        float acc[4] = {0.f, 0.f, 0.f, 0.f};
#pragma unroll 4
        for (int c = 0; c < CC; c++) {
            float cv = sm[S_CS + c * 129 + i];
            float4 av = *(const float4*)(sm + S_AT4 + c * 8 + par * 4);
            acc[0] = fmaf(av.x, cv, acc[0]);
            acc[1] = fmaf(av.y, cv, acc[1]);
            acc[2] = fmaf(av.z, cv, acc[2]);
            acc[3] = fmaf(av.w, cv, acc[3]);
        }
        float* dst = sm + S_WS4 + i * 8 + par * 4;
        dst[0] = acc[0]; dst[1] = acc[1]; dst[2] = acc[2]; dst[3] = acc[3];
    }
    __syncthreads();

    // ---- Phase 7: y[h][j] = sum_i wsum[h][i]*Wv[i][j] ----
    {
        int j = t & 127, par = t >> 7;
        float acc[4] = {0.f, 0.f, 0.f, 0.f};
#pragma unroll 4
        for (int i = 0; i < DD; i++) {
            float wvv = Wv[i * DD + j];
            float4 sv = *(const float4*)(sm + S_WS4 + i * 8 + par * 4);
            acc[0] = fmaf(sv.x, wvv, acc[0]);
            acc[1] = fmaf(sv.y, wvv, acc[1]);
            acc[2] = fmaf(sv.z, wvv, acc[2]);
            acc[3] = fmaf(sv.w, wvv, acc[3]);
        }
#pragma unroll
        for (int m = 0; m < 4; m++) sm[S_YS + (par + 2 * m) * 132 + j] = acc[m];
    }
    __syncthreads();

    // ---- Phase 7b: glimpse[16h+k] = sum_j y[h][j]*Wmv[j][16h+k]; then @Wmo ----
    if (t < DD) {
        int h = t >> 4;
        float acc = 0.f;
#pragma unroll 8
        for (int j = 0; j < DD; j++) acc = fmaf(sm[S_YS + h * 132 + j], Wmv[j * DD + t], acc);
        sm[S_GV + t] = acc;
    }
    __syncthreads();
    if (t < DD) {
        float acc = 0.f;
#pragma unroll 8
        for (int j = 0; j < DD; j++) acc = fmaf(sm[S_GV + j], Wmo[j * DD + t], acc);
        sm[S_GO + t] = acc;
    }
    __syncthreads();

    // ---- Phase 8: stage Wks; gw[i] = sum_j Wks[i][j]*go[j]; logits ----
    for (int p4 = t; p4 < (DD * DD) / 4; p4 += 256) {
        float4 v = ((const float4*)Wks)[p4];
        int base = p4 * 4;
        float* dst = sm + S_WB + (base >> 7) * 129 + (base & 127);
        dst[0] = v.x; dst[1] = v.y; dst[2] = v.z; dst[3] = v.w;
    }
    __syncthreads();
    if (t < DD) {
        float acc = 0.f;
#pragma unroll 8
        for (int j = 0; j < DD; j++) acc = fmaf(sm[S_WB + t * 129 + j], sm[S_GO + j], acc);
        sm[S_GW + t] = acc;
    }
    __syncthreads();
    if (t < 2 * CC) {
        int c = t >> 1, half = t & 1;
        float acc = 0.f;
        int i0 = half * 64;
#pragma unroll 8
        for (int i = i0; i < i0 + 64; i++)
            acc = fmaf(sm[S_CS + c * 129 + i], sm[S_GW + i], acc);
        sm[S_PART + c * 2 + half] = acc;
    }
    __syncthreads();
    if (t < CC) {
        float lg = (sm[S_PART + t * 2] + sm[S_PART + t * 2 + 1]) * 0.08838834764831845f;
        lg = tanhf(lg) * CLIPV;
        sm[S_LGT + t] = (sm[S_VCM + t] != 0.0f) ? NEGV : lg;
    }
    __syncthreads();

    // ---- Phase 8b: argmax (first-index ties) + logsumexp (warp 0) ----
    if (w == 0) {
        float bv = -INFINITY;
        int bi = 0x7fffffff;
        for (int c = lane; c < CC; c += 32) {
            float v = sm[S_LGT + c];
            if (v > bv || (v == bv && c < bi)) { bv = v; bi = c; }
        }
#pragma unroll
        for (int off = 16; off; off >>= 1) {
            float ov = __shfl_down_sync(0xffffffffu, bv, off);
            int oi = __shfl_down_sync(0xffffffffu, bi, off);
            if (ov > bv || (ov == bv && oi < bi)) { bv = ov; bi = oi; }
        }
        bv = __shfl_sync(0xffffffffu, bv, 0);
        bi = __shfl_sync(0xffffffffu, bi, 0);
        float s = 0.f;
        for (int c = lane; c < CC; c += 32) s += expf(sm[S_LGT + c] - bv);
#pragma unroll
        for (int off = 16; off; off >>= 1) s += __shfl_xor_sync(0xffffffffu, s, off);
        if (lane == 0) {
            sm[S_MISC + 0] = (float)bi;
            sm[S_MISC + 1] = bv + logf(s);
        }
    }
    __syncthreads();

    // ---- Phase 9: outputs ----
    const int gid = (int)sm[S_MISC + 0];
    const float mlse = sm[S_MISC + 1];
    float* aug = out + OUT_AUG + (size_t)b * 512;
    float* gout = out + OUT_GEMB + (size_t)b * 128;
    float* cpo = out + OUT_CLU + (size_t)b * CC;
    if (t < DD) {
        float ge = sm[S_CS + gid * 129 + t];
        aug[t]        = isnew ? sm[S_M2 + t] : 0.0f;
        aug[128 + t]  = isnew ? sm[S_CUR + t] : 0.0f;
        aug[256 + t]  = isnew ? ge : 0.0f;
        aug[384 + t]  = isnew ? sm[S_DEP + t] : 0.0f;
        gout[t]       = isnew ? ge : 0.0f;
    }
    if (t < CC) cpo[t] = isnew ? (sm[S_LGT + t] - mlse) : 0.0f;
    if (t == 0) out[OUT_GUID + b] = isnew ? (float)gid : 0.0f;
}

extern "C" void kernel_launch(void* const* d_in, const int* in_sizes, int n_in,
                              void* d_out, int out_size) {
    (void)in_sizes; (void)n_in; (void)out_size;
    const float* depot   = (const float*)d_in[0];
    const float* cluster = (const float*)d_in[1];
    const float* curE    = (const float*)d_in[2];
    const float* node    = (const float*)d_in[3];
    const void*  isnewp  = d_in[4];
    const void*  cmaskp  = d_in[5];
    const void*  vcmp    = d_in[6];
    const void*  maskp   = d_in[7];
    const float* Wq  = (const float*)d_in[8];
    const float* Wk  = (const float*)d_in[9];
    const float* Wv  = (const float*)d_in[10];
    const float* Wks = (const float*)d_in[11];
    const float* Wmq = (const float*)d_in[12];
    const float* Wmk = (const float*)d_in[13];
    const float* Wmv = (const float*)d_in[14];
    const float* Wmo = (const float*)d_in[15];

    cudaFuncSetAttribute(clu_fused_kernel,
                         cudaFuncAttributeMaxDynamicSharedMemorySize, SMEM_BYTES);
    clu_fused_kernel<<<BB, 256, SMEM_BYTES>>>(
        depot, cluster, curE, node, isnewp, cmaskp, vcmp, maskp,
        Wq, Wk, Wv, Wks, Wmq, Wmk, Wmv, Wmo, (float*)d_out);
}

// round 8
// speedup vs baseline: 1.4610x; 1.4610x over previous
#include <cuda_runtime.h>
#include <math.h>

// Problem constants
#define BB 128
#define NN 2000
#define CC 100
#define DD 128
#define HH 8
#define DKK 16
#define NEGV (-1000000000.0f)
#define CLIPV 10.0f

#define SPLIT 16
#define CH (NN / SPLIT)   // 125 nodes per chunk

// Output layout (float32, flattened tuple order)
#define OUT_AUG 0
#define OUT_GEMB 65536
#define OUT_GUID 81920
#define OUT_CLU 82048

// Global scratch for partial masked sums: [2][B][SPLIT][D] = 2 MB
#define G2OFF (BB * SPLIT * DD)
__device__ float g_part[2 * BB * SPLIT * DD];

// Shared memory layout for kernel 2 (float offsets)
#define S_CS 0           // cluster tile [100][129]
#define S_WB 12900       // weight stage [128][129]
#define S_M1 29412
#define S_M2 29540
#define S_CUR 29668
#define S_DEP 29796
#define S_CTX 29924      // [384]
#define S_QV 30308
#define S_QH 30436
#define S_R4 30564       // [128][8]
#define S_U4 31588       // [128][8]
#define S_SC 32612       // [8][104]
#define S_AT4 33444      // [100][8]
#define S_WS4 34244      // [128][8]
#define S_YS 35268       // [8][132]
#define S_GV 36324
#define S_GO 36452
#define S_GW 36580
#define S_PART 36708     // [100][2] + pad
#define S_LGT 36916
#define S_MISC 37020
#define S_VCM 37036
#define SMEM_FLOATS 37140
#define SMEM_BYTES (SMEM_FLOATS * 4)

__device__ __forceinline__ bool rdmask(const void* p, int flag, long long i) {
    if (flag == 0) return ((const unsigned char*)p)[i] != 0;
    if (flag == 1) return ((const int*)p)[i] != 0;
    return ((const float*)p)[i] != 0.0f;
}

// ============================================================================
// Kernel 1: masked partial sums over node_embeddings. grid = B*SPLIT.
// ============================================================================
__global__ void __launch_bounds__(256)
means_kernel(const float* __restrict__ node, const void* __restrict__ maskp,
             const void* __restrict__ cmaskp) {
    __shared__ float red[2 * 8 * 128];
    __shared__ unsigned char mloc[CH], cmloc[CH];
    const int b = blockIdx.x >> 4;
    const int s = blockIdx.x & 15;
    const int t = threadIdx.x;
    const int lane = t & 31;
    const int w = t >> 5;

    // sniff bool serialization dtype (byte / int32 / float32)
    unsigned wword = ((const unsigned*)maskp)[t];
    int o1  = __syncthreads_or((wword & 0x0000ff00u) ? 1 : 0);
    int o23 = __syncthreads_or((wword & 0xffff0000u) ? 1 : 0);
    const int flag = o1 ? 0 : (o23 ? 2 : 1);

    const long long mbase = (long long)b * NN + s * CH;
    for (int n = t; n < CH; n += 256) {
        mloc[n]  = rdmask(maskp,  flag, mbase + n) ? 1 : 0;
        cmloc[n] = rdmask(cmaskp, flag, mbase + n) ? 1 : 0;
    }
    __syncthreads();

    const float* np_ = node + ((size_t)b * NN + (size_t)s * CH) * DD;
    const int d0 = lane * 4;
    float4 a1 = make_float4(0.f, 0.f, 0.f, 0.f);
    float4 a2 = make_float4(0.f, 0.f, 0.f, 0.f);
#pragma unroll 8
    for (int n = w; n < CH; n += 8) {
        float4 v = *(const float4*)(np_ + (size_t)n * DD + d0);
        bool m = mloc[n] != 0;
        bool mc = (mloc[n] | cmloc[n]) != 0;
        if (!m)  { a1.x += v.x; a1.y += v.y; a1.z += v.z; a1.w += v.w; }
        if (!mc) { a2.x += v.x; a2.y += v.y; a2.z += v.z; a2.w += v.w; }
    }
    int o = w * 128 + d0;
    red[o] = a1.x; red[o + 1] = a1.y; red[o + 2] = a1.z; red[o + 3] = a1.w;
    red[1024 + o] = a2.x; red[1024 + o + 1] = a2.y;
    red[1024 + o + 2] = a2.z; red[1024 + o + 3] = a2.w;
    __syncthreads();
    if (t < DD) {
        float s1 = 0.f, s2 = 0.f;
#pragma unroll
        for (int ww = 0; ww < 8; ww++) {
            s1 += red[ww * 128 + t];
            s2 += red[1024 + ww * 128 + t];
        }
        size_t idx = (size_t)(b * SPLIT + s) * DD + t;
        g_part[idx] = s1;
        g_part[G2OFF + idx] = s2;
    }
}

// ============================================================================
// Kernel 2: per-batch fused compute. grid = B.
// ============================================================================
__global__ void __launch_bounds__(256, 1)
clu_fused_kernel(const float* __restrict__ depot, const float* __restrict__ cluster,
                 const float* __restrict__ curE,
                 const void* __restrict__ isnewp, const void* __restrict__ cmaskp,
                 const void* __restrict__ vcmp, const void* __restrict__ maskp,
                 const float* __restrict__ Wq, const float* __restrict__ Wk,
                 const float* __restrict__ Wv, const float* __restrict__ Wks,
                 const float* __restrict__ Wmq, const float* __restrict__ Wmk,
                 const float* __restrict__ Wmv, const float* __restrict__ Wmo,
                 float* __restrict__ out) {
    extern __shared__ float sm[];
    const int b = blockIdx.x;
    const int t = threadIdx.x;
    const int lane = t & 31;
    const int w = t >> 5;

    // sniff bool dtype
    unsigned wword = ((const unsigned*)maskp)[t];
    int o1  = __syncthreads_or((wword & 0x0000ff00u) ? 1 : 0);
    int o23 = __syncthreads_or((wword & 0xffff0000u) ? 1 : 0);
    const int flag = o1 ? 0 : (o23 ? 2 : 1);

    // small loads + cluster tile -> smem
    if (t < DD) {
        sm[S_CUR + t] = curE[b * DD + t];
        sm[S_DEP + t] = depot[b * DD + t];
    }
    if (t < CC) sm[S_VCM + t] = rdmask(vcmp, flag, (long long)b * CC + t) ? 1.0f : 0.0f;
    const bool isnew = rdmask(isnewp, flag, b);

    {
        const float* cp = cluster + (size_t)b * CC * DD;
        for (int p4 = t; p4 < (CC * DD) / 4; p4 += 256) {
            float4 v = ((const float4*)cp)[p4];
            int base = p4 * 4;
            float* dst = sm + S_CS + (base >> 7) * 129 + (base & 127);
            dst[0] = v.x; dst[1] = v.y; dst[2] = v.z; dst[3] = v.w;
        }
    }

    // means: reduce SPLIT partials from global scratch
    if (t < DD) {
        float s1 = 0.f, s2 = 0.f;
#pragma unroll
        for (int s = 0; s < SPLIT; s++) {
            size_t idx = (size_t)(b * SPLIT + s) * DD + t;
            s1 += g_part[idx];
            s2 += g_part[G2OFF + idx];
        }
        float m1 = s1 * (1.0f / NN), m2 = s2 * (1.0f / NN);
        sm[S_M1 + t] = m1;
        sm[S_M2 + t] = m2;
        sm[S_CTX + t] = m1;
        sm[S_CTX + 128 + t] = sm[S_CUR + t];  // written by this same thread above
        sm[S_CTX + 256 + t] = sm[S_DEP + t];
    }
    __syncthreads();

    // vcm[0] adjustment (warp 0)
    if (w == 0) {
        bool ok = true;
        for (int c = 1 + lane; c < CC; c += 32) ok = ok && (sm[S_VCM + c] != 0.0f);
        bool allv = __all_sync(0xffffffffu, ok);
        if (lane == 0 && isnew) sm[S_VCM + 0] = allv ? 0.0f : 1.0f;
    }

    // ---- q = ctx @ Wq (4 independent accumulator chains) ----
    if (t < DD) {
        float a0 = 0.f, a1 = 0.f, a2 = 0.f, a3 = 0.f;
#pragma unroll 8
        for (int i = 0; i < 3 * DD; i += 4) {
            a0 = fmaf(sm[S_CTX + i],     Wq[(i)     * DD + t], a0);
            a1 = fmaf(sm[S_CTX + i + 1], Wq[(i + 1) * DD + t], a1);
            a2 = fmaf(sm[S_CTX + i + 2], Wq[(i + 2) * DD + t], a2);
            a3 = fmaf(sm[S_CTX + i + 3], Wq[(i + 3) * DD + t], a3);
        }
        sm[S_QV + t] = (a0 + a1) + (a2 + a3);
    }
    __syncthreads();
    // ---- qh = q @ Wmq ----
    if (t < DD) {
        float a0 = 0.f, a1 = 0.f, a2 = 0.f, a3 = 0.f;
#pragma unroll 8
        for (int j = 0; j < DD; j += 4) {
            a0 = fmaf(sm[S_QV + j],     Wmq[(j)     * DD + t], a0);
            a1 = fmaf(sm[S_QV + j + 1], Wmq[(j + 1) * DD + t], a1);
            a2 = fmaf(sm[S_QV + j + 2], Wmq[(j + 2) * DD + t], a2);
            a3 = fmaf(sm[S_QV + j + 3], Wmq[(j + 3) * DD + t], a3);
        }
        sm[S_QH + t] = (a0 + a1) + (a2 + a3);
    }
    __syncthreads();

    // ---- stage Wmk; r[h][j] = sum_k Wmk[j][16h+k]*qh[16h+k] ----
    for (int p4 = t; p4 < (DD * DD) / 4; p4 += 256) {
        float4 v = ((const float4*)Wmk)[p4];
        int base = p4 * 4;
        float* dst = sm + S_WB + (base >> 7) * 129 + (base & 127);
        dst[0] = v.x; dst[1] = v.y; dst[2] = v.z; dst[3] = v.w;
    }
    __syncthreads();
    {
        int j = t & 127, par = t >> 7;
        float racc[4];
#pragma unroll
        for (int m = 0; m < 4; m++) {
            int h = par + 2 * m;
            float a = 0.f;
#pragma unroll
            for (int k = 0; k < 16; k++)
                a = fmaf(sm[S_WB + j * 129 + 16 * h + k], sm[S_QH + 16 * h + k], a);
            racc[m] = a;
        }
        float* dst = sm + S_R4 + j * 8 + par * 4;
        dst[0] = racc[0]; dst[1] = racc[1]; dst[2] = racc[2]; dst[3] = racc[3];
    }
    __syncthreads();

    // ---- stage Wk; u[h][i] = sum_j Wk[i][j]*r[h][j] ----
    for (int p4 = t; p4 < (DD * DD) / 4; p4 += 256) {
        float4 v = ((const float4*)Wk)[p4];
        int base = p4 * 4;
        float* dst = sm + S_WB + (base >> 7) * 129 + (base & 127);
        dst[0] = v.x; dst[1] = v.y; dst[2] = v.z; dst[3] = v.w;
    }
    __syncthreads();
    {
        int i = t & 127, par = t >> 7;
        float acc[4] = {0.f, 0.f, 0.f, 0.f};
#pragma unroll 4
        for (int j = 0; j < DD; j++) {
            float wv_ = sm[S_WB + i * 129 + j];
            float4 rv = *(const float4*)(sm + S_R4 + j * 8 + par * 4);
            acc[0] = fmaf(wv_, rv.x, acc[0]);
            acc[1] = fmaf(wv_, rv.y, acc[1]);
            acc[2] = fmaf(wv_, rv.z, acc[2]);
            acc[3] = fmaf(wv_, rv.w, acc[3]);
        }
        float* dst = sm + S_U4 + i * 8 + par * 4;
        dst[0] = acc[0]; dst[1] = acc[1]; dst[2] = acc[2]; dst[3] = acc[3];
    }
    __syncthreads();

    // ---- scores[c][h] = cluster[c]·u[h] * 0.25, masked ----
    if (t < 2 * CC) {
        int c = t >> 1, par = t & 1;
        float acc[4] = {0.f, 0.f, 0.f, 0.f};
#pragma unroll 4
        for (int i = 0; i < DD; i++) {
            float cv = sm[S_CS + c * 129 + i];
            float4 uu = *(const float4*)(sm + S_U4 + i * 8 + par * 4);
            acc[0] = fmaf(cv, uu.x, acc[0]);
            acc[1] = fmaf(cv, uu.y, acc[1]);
            acc[2] = fmaf(cv, uu.z, acc[2]);
            acc[3] = fmaf(cv, uu.w, acc[3]);
        }
        bool msk = sm[S_VCM + c] != 0.0f;
#pragma unroll
        for (int m = 0; m < 4; m++) {
            int h = par + 2 * m;
            sm[S_SC + h * 104 + c] = msk ? NEGV : acc[m] * 0.25f;
        }
    }
    __syncthreads();

    // ---- softmax over c, per head (warp h) ----
    {
        int h = w;
        float mx = -INFINITY;
        for (int c = lane; c < CC; c += 32) mx = fmaxf(mx, sm[S_SC + h * 104 + c]);
#pragma unroll
        for (int off = 16; off; off >>= 1) mx = fmaxf(mx, __shfl_xor_sync(0xffffffffu, mx, off));
        float s = 0.f;
        for (int c = lane; c < CC; c += 32) {
            float e = expf(sm[S_SC + h * 104 + c] - mx);
            s += e;
            sm[S_AT4 + c * 8 + (h & 1) * 4 + (h >> 1)] = e;
        }
#pragma unroll
        for (int off = 16; off; off >>= 1) s += __shfl_xor_sync(0xffffffffu, s, off);
        float inv = 1.0f / s;
        for (int c = lane; c < CC; c += 32)
            sm[S_AT4 + c * 8 + (h & 1) * 4 + (h >> 1)] *= inv;
    }
    __syncthreads();

    // ---- wsum[h][i] = sum_c attn[h][c]*cluster[c][i] ----
    {
        int i = t & 127, par = t >> 7;
        float acc[4] = {0.f, 0.f, 0.f, 0.f};
#pragma unroll 4
        for (int c = 0; c < CC; c++) {
            float cv = sm[S_CS + c * 129 + i];
            float4 av = *(const float4*)(sm + S_AT4 + c * 8 + par * 4);
            acc[0] = fmaf(av.x, cv, acc[0]);
            acc[1] = fmaf(av.y, cv, acc[1]);
            acc[2] = fmaf(av.z, cv, acc[2]);
            acc[3] = fmaf(av.w, cv, acc[3]);
        }
        float* dst = sm + S_WS4 + i * 8 + par * 4;
        dst[0] = acc[0]; dst[1] = acc[1]; dst[2] = acc[2]; dst[3] = acc[3];
    }
    __syncthreads();

    // ---- y[h][j] = sum_i wsum[h][i]*Wv[i][j] ----
    {
        int j = t & 127, par = t >> 7;
        float acc[4] = {0.f, 0.f, 0.f, 0.f};
#pragma unroll 4
        for (int i = 0; i < DD; i++) {
            float wvv = Wv[i * DD + j];
            float4 sv = *(const float4*)(sm + S_WS4 + i * 8 + par * 4);
            acc[0] = fmaf(sv.x, wvv, acc[0]);
            acc[1] = fmaf(sv.y, wvv, acc[1]);
            acc[2] = fmaf(sv.z, wvv, acc[2]);
            acc[3] = fmaf(sv.w, wvv, acc[3]);
        }
#pragma unroll
        for (int m = 0; m < 4; m++) sm[S_YS + (par + 2 * m) * 132 + j] = acc[m];
    }
    __syncthreads();

    // ---- glimpse[16h+k] = sum_j y[h][j]*Wmv[j][16h+k] ----
    if (t < DD) {
        int h = t >> 4;
        float a0 = 0.f, a1 = 0.f, a2 = 0.f, a3 = 0.f;
#pragma unroll 8
        for (int j = 0; j < DD; j += 4) {
            a0 = fmaf(sm[S_YS + h * 132 + j],     Wmv[(j)     * DD + t], a0);
            a1 = fmaf(sm[S_YS + h * 132 + j + 1], Wmv[(j + 1) * DD + t], a1);
            a2 = fmaf(sm[S_YS + h * 132 + j + 2], Wmv[(j + 2) * DD + t], a2);
            a3 = fmaf(sm[S_YS + h * 132 + j + 3], Wmv[(j + 3) * DD + t], a3);
        }
        sm[S_GV + t] = (a0 + a1) + (a2 + a3);
    }
    __syncthreads();
    // ---- go = glimpse @ Wmo ----
    if (t < DD) {
        float a0 = 0.f, a1 = 0.f, a2 = 0.f, a3 = 0.f;
#pragma unroll 8
        for (int j = 0; j < DD; j += 4) {
            a0 = fmaf(sm[S_GV + j],     Wmo[(j)     * DD + t], a0);
            a1 = fmaf(sm[S_GV + j + 1], Wmo[(j + 1) * DD + t], a1);
            a2 = fmaf(sm[S_GV + j + 2], Wmo[(j + 2) * DD + t], a2);
            a3 = fmaf(sm[S_GV + j + 3], Wmo[(j + 3) * DD + t], a3);
        }
        sm[S_GO + t] = (a0 + a1) + (a2 + a3);
    }
    __syncthreads();

    // ---- stage Wks; gw[i] = sum_j Wks[i][j]*go[j]; logits ----
    for (int p4 = t; p4 < (DD * DD) / 4; p4 += 256) {
        float4 v = ((const float4*)Wks)[p4];
        int base = p4 * 4;
        float* dst = sm + S_WB + (base >> 7) * 129 + (base & 127);
        dst[0] = v.x; dst[1] = v.y; dst[2] = v.z; dst[3] = v.w;
    }
    __syncthreads();
    if (t < DD) {
        float a0 = 0.f, a1 = 0.f, a2 = 0.f, a3 = 0.f;
#pragma unroll 8
        for (int j = 0; j < DD; j += 4) {
            a0 = fmaf(sm[S_WB + t * 129 + j],     sm[S_GO + j],     a0);
            a1 = fmaf(sm[S_WB + t * 129 + j + 1], sm[S_GO + j + 1], a1);
            a2 = fmaf(sm[S_WB + t * 129 + j + 2], sm[S_GO + j + 2], a2);
            a3 = fmaf(sm[S_WB + t * 129 + j + 3], sm[S_GO + j + 3], a3);
        }
        sm[S_GW + t] = (a0 + a1) + (a2 + a3);
    }
    __syncthreads();
    if (t < 2 * CC) {
        int c = t >> 1, half = t & 1;
        float acc = 0.f;
        int i0 = half * 64;
#pragma unroll 8
        for (int i = i0; i < i0 + 64; i++)
            acc = fmaf(sm[S_CS + c * 129 + i], sm[S_GW + i], acc);
        sm[S_PART + c * 2 + half] = acc;
    }
    __syncthreads();
    if (t < CC) {
        float lg = (sm[S_PART + t * 2] + sm[S_PART + t * 2 + 1]) * 0.08838834764831845f;
        lg = tanhf(lg) * CLIPV;
        sm[S_LGT + t] = (sm[S_VCM + t] != 0.0f) ? NEGV : lg;
    }
    __syncthreads();

    // ---- argmax (first-index ties) + logsumexp (warp 0) ----
    if (w == 0) {
        float bv = -INFINITY;
        int bi = 0x7fffffff;
        for (int c = lane; c < CC; c += 32) {
            float v = sm[S_LGT + c];
            if (v > bv || (v == bv && c < bi)) { bv = v; bi = c; }
        }
#pragma unroll
        for (int off = 16; off; off >>= 1) {
            float ov = __shfl_down_sync(0xffffffffu, bv, off);
            int oi = __shfl_down_sync(0xffffffffu, bi, off);
            if (ov > bv || (ov == bv && oi < bi)) { bv = ov; bi = oi; }
        }
        bv = __shfl_sync(0xffffffffu, bv, 0);
        bi = __shfl_sync(0xffffffffu, bi, 0);
        float s = 0.f;
        for (int c = lane; c < CC; c += 32) s += expf(sm[S_LGT + c] - bv);
#pragma unroll
        for (int off = 16; off; off >>= 1) s += __shfl_xor_sync(0xffffffffu, s, off);
        if (lane == 0) {
            sm[S_MISC + 0] = (float)bi;
            sm[S_MISC + 1] = bv + logf(s);
        }
    }
    __syncthreads();

    // ---- outputs ----
    const int gid = (int)sm[S_MISC + 0];
    const float mlse = sm[S_MISC + 1];
    float* aug = out + OUT_AUG + (size_t)b * 512;
    float* gout = out + OUT_GEMB + (size_t)b * 128;
    float* cpo = out + OUT_CLU + (size_t)b * CC;
    if (t < DD) {
        float ge = sm[S_CS + gid * 129 + t];
        aug[t]        = isnew ? sm[S_M2 + t] : 0.0f;
        aug[128 + t]  = isnew ? sm[S_CUR + t] : 0.0f;
        aug[256 + t]  = isnew ? ge : 0.0f;
        aug[384 + t]  = isnew ? sm[S_DEP + t] : 0.0f;
        gout[t]       = isnew ? ge : 0.0f;
    }
    if (t < CC) cpo[t] = isnew ? (sm[S_LGT + t] - mlse) : 0.0f;
    if (t == 0) out[OUT_GUID + b] = isnew ? (float)gid : 0.0f;
}

extern "C" void kernel_launch(void* const* d_in, const int* in_sizes, int n_in,
                              void* d_out, int out_size) {
    (void)in_sizes; (void)n_in; (void)out_size;
    const float* depot   = (const float*)d_in[0];
    const float* cluster = (const float*)d_in[1];
    const float* curE    = (const float*)d_in[2];
    const float* node    = (const float*)d_in[3];
    const void*  isnewp  = d_in[4];
    const void*  cmaskp  = d_in[5];
    const void*  vcmp    = d_in[6];
    const void*  maskp   = d_in[7];
    const float* Wq  = (const float*)d_in[8];
    const float* Wk  = (const float*)d_in[9];
    const float* Wv  = (const float*)d_in[10];
    const float* Wks = (const float*)d_in[11];
    const float* Wmq = (const float*)d_in[12];
    const float* Wmk = (const float*)d_in[13];
    const float* Wmv = (const float*)d_in[14];
    const float* Wmo = (const float*)d_in[15];

    means_kernel<<<BB * SPLIT, 256>>>(node, maskp, cmaskp);

    cudaFuncSetAttribute(clu_fused_kernel,
                         cudaFuncAttributeMaxDynamicSharedMemorySize, SMEM_BYTES);
    clu_fused_kernel<<<BB, 256, SMEM_BYTES>>>(
        depot, cluster, curE, isnewp, cmaskp, vcmp, maskp,
        Wq, Wk, Wv, Wks, Wmq, Wmk, Wmv, Wmo, (float*)d_out);
}

// round 9
// speedup vs baseline: 2.1299x; 1.4579x over previous
#include <cuda_runtime.h>
#include <math.h>

// Problem constants
#define BB 128
#define NN 2000
#define CC 100
#define DD 128
#define HH 8
#define DKK 16
#define NEGV (-1000000000.0f)
#define CLIPV 10.0f

#define SPLIT 16
#define CH (NN / SPLIT)   // 125 nodes per chunk

// Output layout (float32, flattened tuple order)
#define OUT_AUG 0
#define OUT_GEMB 65536
#define OUT_GUID 81920
#define OUT_CLU 82048

// Global scratch for partial masked sums: [2][B][SPLIT][D] = 2 MB
#define G2OFF (BB * SPLIT * DD)
__device__ float g_part[2 * BB * SPLIT * DD];

// ---------------- Kernel 2 shared memory layout (float offsets) ----------------
#define S_CS   0        // cluster tile [100][129]
#define S_WA   12900    // weight buffer A [128][129]
#define S_WB2  29412    // weight buffer B [128][129]
#define S_M1   45924
#define S_M2   46052
#define S_CUR  46180
#define S_DEP  46308
#define S_QV   46436
#define S_QH   46564
#define S_R4   46692    // r [128][8] (h plain order)
#define S_U4   47716    // u [128][8]
#define S_SC   48740    // scores [8][104]
#define S_AT4  49572    // attn [100][8]
#define S_WS4  50372    // wsum [128][8]
#define S_YS   51396    // y [8][132]
#define S_GV   52452
#define S_GO   52580
#define S_GW   52708
#define S_PART 52836    // [100][2] + pad
#define S_LGT  53044
#define S_MISC 53148
#define S_VCM  53150
#define SMEM_FLOATS 53256
#define SMEM_BYTES (SMEM_FLOATS * 4)

__device__ __forceinline__ bool rdmask(const void* p, int flag, long long i) {
    if (flag == 0) return ((const unsigned char*)p)[i] != 0;
    if (flag == 1) return ((const int*)p)[i] != 0;
    return ((const float*)p)[i] != 0.0f;
}

// Stage a 128x128 row-major global matrix into a [128][129] smem buffer.
// 128 threads, idx in [0,128). 32 independent float4 loads per thread.
__device__ __forceinline__ void stage128(const float* __restrict__ src,
                                         float* __restrict__ dst, int idx) {
#pragma unroll
    for (int k = 0; k < 32; k++) {
        int p4 = k * 128 + idx;
        float4 v = ((const float4*)src)[p4];
        int base = p4 * 4;
        float* d = dst + (base >> 7) * 129 + (base & 127);
        d[0] = v.x; d[1] = v.y; d[2] = v.z; d[3] = v.w;
    }
}

// Same but with 256 threads (16 float4 per thread).
__device__ __forceinline__ void stage256(const float* __restrict__ src,
                                         float* __restrict__ dst, int t) {
#pragma unroll
    for (int k = 0; k < 16; k++) {
        int p4 = k * 256 + t;
        float4 v = ((const float4*)src)[p4];
        int base = p4 * 4;
        float* d = dst + (base >> 7) * 129 + (base & 127);
        d[0] = v.x; d[1] = v.y; d[2] = v.z; d[3] = v.w;
    }
}

// ============================================================================
// Kernel 1: masked partial sums over node_embeddings. grid = B*SPLIT.
// ============================================================================
__global__ void __launch_bounds__(256)
means_kernel(const float* __restrict__ node, const void* __restrict__ maskp,
             const void* __restrict__ cmaskp) {
    __shared__ float red[2 * 8 * 128];
    __shared__ unsigned char mloc[CH], cmloc[CH];
    const int b = blockIdx.x >> 4;
    const int s = blockIdx.x & 15;
    const int t = threadIdx.x;
    const int lane = t & 31;
    const int w = t >> 5;

    // sniff bool serialization dtype (byte / int32 / float32)
    unsigned wword = ((const unsigned*)maskp)[t];
    int o1  = __syncthreads_or((wword & 0x0000ff00u) ? 1 : 0);
    int o23 = __syncthreads_or((wword & 0xffff0000u) ? 1 : 0);
    const int flag = o1 ? 0 : (o23 ? 2 : 1);

    const long long mbase = (long long)b * NN + s * CH;
    for (int n = t; n < CH; n += 256) {
        mloc[n]  = rdmask(maskp,  flag, mbase + n) ? 1 : 0;
        cmloc[n] = rdmask(cmaskp, flag, mbase + n) ? 1 : 0;
    }
    __syncthreads();

    const float* np_ = node + ((size_t)b * NN + (size_t)s * CH) * DD;
    const int d0 = lane * 4;
    float4 a1 = make_float4(0.f, 0.f, 0.f, 0.f);
    float4 a2 = make_float4(0.f, 0.f, 0.f, 0.f);
#pragma unroll 8
    for (int n = w; n < CH; n += 8) {
        float4 v = *(const float4*)(np_ + (size_t)n * DD + d0);
        bool m = mloc[n] != 0;
        bool mc = (mloc[n] | cmloc[n]) != 0;
        if (!m)  { a1.x += v.x; a1.y += v.y; a1.z += v.z; a1.w += v.w; }
        if (!mc) { a2.x += v.x; a2.y += v.y; a2.z += v.z; a2.w += v.w; }
    }
    int o = w * 128 + d0;
    red[o] = a1.x; red[o + 1] = a1.y; red[o + 2] = a1.z; red[o + 3] = a1.w;
    red[1024 + o] = a2.x; red[1024 + o + 1] = a2.y;
    red[1024 + o + 2] = a2.z; red[1024 + o + 3] = a2.w;
    __syncthreads();
    if (t < DD) {
        float s1 = 0.f, s2 = 0.f;
#pragma unroll
        for (int ww = 0; ww < 8; ww++) {
            s1 += red[ww * 128 + t];
            s2 += red[1024 + ww * 128 + t];
        }
        size_t idx = (size_t)(b * SPLIT + s) * DD + t;
        g_part[idx] = s1;
        g_part[G2OFF + idx] = s2;
    }
}

// ============================================================================
// Kernel 2: per-batch fused compute, smem-staged weights, warp-specialized.
// grid = B, block = 256.
// ============================================================================
__global__ void __launch_bounds__(256, 1)
clu_fused_kernel(const float* __restrict__ depot, const float* __restrict__ cluster,
                 const float* __restrict__ curE,
                 const void* __restrict__ isnewp,
                 const void* __restrict__ vcmp, const void* __restrict__ maskp,
                 const float* __restrict__ Wq, const float* __restrict__ Wk,
                 const float* __restrict__ Wv, const float* __restrict__ Wks,
                 const float* __restrict__ Wmq, const float* __restrict__ Wmk,
                 const float* __restrict__ Wmv, const float* __restrict__ Wmo,
                 float* __restrict__ out) {
    extern __shared__ float sm[];
    const int b = blockIdx.x;
    const int t = threadIdx.x;
    const int lane = t & 31;
    const int w = t >> 5;
    const int sidx = t - 128;   // stage index for warps 4-7

    // sniff bool dtype
    unsigned wword = ((const unsigned*)maskp)[t];
    int o1  = __syncthreads_or((wword & 0x0000ff00u) ? 1 : 0);
    int o23 = __syncthreads_or((wword & 0xffff0000u) ? 1 : 0);
    const int flag = o1 ? 0 : (o23 ? 2 : 1);
    const bool isnew = rdmask(isnewp, flag, b);

    // ================= P0: all initial loads + stage Wq part0 -> A =========
    if (t < DD) {
        sm[S_CUR + t] = curE[b * DD + t];
        sm[S_DEP + t] = depot[b * DD + t];
    }
    if (t < CC) sm[S_VCM + t] = rdmask(vcmp, flag, (long long)b * CC + t) ? 1.0f : 0.0f;
    {
        const float* cp = cluster + (size_t)b * CC * DD;
#pragma unroll
        for (int p4 = t; p4 < (CC * DD) / 4; p4 += 256) {
            float4 v = ((const float4*)cp)[p4];
            int base = p4 * 4;
            float* dst = sm + S_CS + (base >> 7) * 129 + (base & 127);
            dst[0] = v.x; dst[1] = v.y; dst[2] = v.z; dst[3] = v.w;
        }
    }
    if (t < DD) {  // means: reduce SPLIT partials
        float s1 = 0.f, s2 = 0.f;
#pragma unroll
        for (int s = 0; s < SPLIT; s++) {
            size_t idx = (size_t)(b * SPLIT + s) * DD + t;
            s1 += g_part[idx];
            s2 += g_part[G2OFF + idx];
        }
        sm[S_M1 + t] = s1 * (1.0f / NN);
        sm[S_M2 + t] = s2 * (1.0f / NN);
    }
    stage256(Wq, sm + S_WA, t);
    __syncthreads();

    float qa = 0.f;  // q accumulator (lives in threads t<128 across P1-P3)

    // ================= P1: q += m1 @ Wq0 (A)   ||  stage Wq1 -> B ==========
    if (w < 4) {
        float a0 = 0.f, a1 = 0.f, a2 = 0.f, a3 = 0.f;
#pragma unroll 8
        for (int i = 0; i < DD; i += 4) {
            a0 = fmaf(sm[S_M1 + i],     sm[S_WA + (i)     * 129 + t], a0);
            a1 = fmaf(sm[S_M1 + i + 1], sm[S_WA + (i + 1) * 129 + t], a1);
            a2 = fmaf(sm[S_M1 + i + 2], sm[S_WA + (i + 2) * 129 + t], a2);
            a3 = fmaf(sm[S_M1 + i + 3], sm[S_WA + (i + 3) * 129 + t], a3);
        }
        qa += (a0 + a1) + (a2 + a3);
    } else {
        stage128(Wq + DD * DD, sm + S_WB2, sidx);
        if (w == 4) {  // vcm[0] fix (warp 4, full warp)
            bool ok = true;
            for (int c = 1 + lane; c < CC; c += 32) ok = ok && (sm[S_VCM + c] != 0.0f);
            bool allv = __all_sync(0xffffffffu, ok);
            if (lane == 0 && isnew) sm[S_VCM + 0] = allv ? 0.0f : 1.0f;
        }
    }
    __syncthreads();

    // ================= P2: q += cur @ Wq1 (B)  ||  stage Wq2 -> A ==========
    if (w < 4) {
        float a0 = 0.f, a1 = 0.f, a2 = 0.f, a3 = 0.f;
#pragma unroll 8
        for (int i = 0; i < DD; i += 4) {
            a0 = fmaf(sm[S_CUR + i],     sm[S_WB2 + (i)     * 129 + t], a0);
            a1 = fmaf(sm[S_CUR + i + 1], sm[S_WB2 + (i + 1) * 129 + t], a1);
            a2 = fmaf(sm[S_CUR + i + 2], sm[S_WB2 + (i + 2) * 129 + t], a2);
            a3 = fmaf(sm[S_CUR + i + 3], sm[S_WB2 + (i + 3) * 129 + t], a3);
        }
        qa += (a0 + a1) + (a2 + a3);
    } else {
        stage128(Wq + 2 * DD * DD, sm + S_WA, sidx);
    }
    __syncthreads();

    // ================= P3: q += dep @ Wq2 (A)  ||  stage Wmq -> B ==========
    if (w < 4) {
        float a0 = 0.f, a1 = 0.f, a2 = 0.f, a3 = 0.f;
#pragma unroll 8
        for (int i = 0; i < DD; i += 4) {
            a0 = fmaf(sm[S_DEP + i],     sm[S_WA + (i)     * 129 + t], a0);
            a1 = fmaf(sm[S_DEP + i + 1], sm[S_WA + (i + 1) * 129 + t], a1);
            a2 = fmaf(sm[S_DEP + i + 2], sm[S_WA + (i + 2) * 129 + t], a2);
            a3 = fmaf(sm[S_DEP + i + 3], sm[S_WA + (i + 3) * 129 + t], a3);
        }
        qa += (a0 + a1) + (a2 + a3);
        sm[S_QV + t] = qa;
    } else {
        stage128(Wmq, sm + S_WB2, sidx);
    }
    __syncthreads();

    // ================= P4: qh = q @ Wmq (B)    ||  stage Wmk -> A ==========
    if (w < 4) {
        float a0 = 0.f, a1 = 0.f, a2 = 0.f, a3 = 0.f;
#pragma unroll 8
        for (int j = 0; j < DD; j += 4) {
            a0 = fmaf(sm[S_QV + j],     sm[S_WB2 + (j)     * 129 + t], a0);
            a1 = fmaf(sm[S_QV + j + 1], sm[S_WB2 + (j + 1) * 129 + t], a1);
            a2 = fmaf(sm[S_QV + j + 2], sm[S_WB2 + (j + 2) * 129 + t], a2);
            a3 = fmaf(sm[S_QV + j + 3], sm[S_WB2 + (j + 3) * 129 + t], a3);
        }
        sm[S_QH + t] = (a0 + a1) + (a2 + a3);
    } else {
        stage128(Wmk, sm + S_WA, sidx);
    }
    __syncthreads();

    // ===== P5: r[h][j=t] = sum_k Wmk[j][16h+k]*qh[16h+k] (A) || stage Wk->B =
    if (w < 4) {
#pragma unroll
        for (int h = 0; h < HH; h++) {
            float a = 0.f;
#pragma unroll
            for (int k = 0; k < 16; k++)
                a = fmaf(sm[S_WA + t * 129 + 16 * h + k], sm[S_QH + 16 * h + k], a);
            sm[S_R4 + t * 8 + h] = a;
        }
    } else {
        stage128(Wk, sm + S_WB2, sidx);
    }
    __syncthreads();

    // ================= P6: u[h][i] = sum_j Wk[i][j]*r[h][j] (B, ALL) =======
    {
        int i = t & 127, par = t >> 7;
        float acc[4] = {0.f, 0.f, 0.f, 0.f};
#pragma unroll 4
        for (int j = 0; j < DD; j++) {
            float wv_ = sm[S_WB2 + i * 129 + j];
            float4 rv = *(const float4*)(sm + S_R4 + j * 8 + par * 4);
            acc[0] = fmaf(wv_, rv.x, acc[0]);
            acc[1] = fmaf(wv_, rv.y, acc[1]);
            acc[2] = fmaf(wv_, rv.z, acc[2]);
            acc[3] = fmaf(wv_, rv.w, acc[3]);
        }
        *(float4*)(sm + S_U4 + i * 8 + par * 4) =
            make_float4(acc[0], acc[1], acc[2], acc[3]);
    }
    __syncthreads();

    // ======= P7: scores[c=t][h] (t<100)  ||  stage Wv -> A (w>=4) ==========
    if (t < CC) {
        float acc[8] = {0.f, 0.f, 0.f, 0.f, 0.f, 0.f, 0.f, 0.f};
#pragma unroll 4
        for (int i = 0; i < DD; i++) {
            float cv = sm[S_CS + t * 129 + i];
            float4 u0 = *(const float4*)(sm + S_U4 + i * 8);
            float4 u1 = *(const float4*)(sm + S_U4 + i * 8 + 4);
            acc[0] = fmaf(cv, u0.x, acc[0]);
            acc[1] = fmaf(cv, u0.y, acc[1]);
            acc[2] = fmaf(cv, u0.z, acc[2]);
            acc[3] = fmaf(cv, u0.w, acc[3]);
            acc[4] = fmaf(cv, u1.x, acc[4]);
            acc[5] = fmaf(cv, u1.y, acc[5]);
            acc[6] = fmaf(cv, u1.z, acc[6]);
            acc[7] = fmaf(cv, u1.w, acc[7]);
        }
        bool msk = sm[S_VCM + t] != 0.0f;
#pragma unroll
        for (int h = 0; h < HH; h++)
            sm[S_SC + h * 104 + t] = msk ? NEGV : acc[h] * 0.25f;
    } else if (w >= 4) {
        stage128(Wv, sm + S_WA, sidx);
    }
    __syncthreads();

    // ======= P8: softmax (warps 0-3, 2 heads each)  ||  stage Wmv -> B =====
    if (w < 4) {
#pragma unroll
        for (int hh = 0; hh < 2; hh++) {
            int h = w + hh * 4;
            float mx = -INFINITY;
            for (int c = lane; c < CC; c += 32) mx = fmaxf(mx, sm[S_SC + h * 104 + c]);
#pragma unroll
            for (int off = 16; off; off >>= 1)
                mx = fmaxf(mx, __shfl_xor_sync(0xffffffffu, mx, off));
            float s = 0.f;
            for (int c = lane; c < CC; c += 32) {
                float e = expf(sm[S_SC + h * 104 + c] - mx);
                s += e;
                sm[S_AT4 + c * 8 + h] = e;
            }
#pragma unroll
            for (int off = 16; off; off >>= 1) s += __shfl_xor_sync(0xffffffffu, s, off);
            float inv = 1.0f / s;
            for (int c = lane; c < CC; c += 32) sm[S_AT4 + c * 8 + h] *= inv;
        }
    } else {
        stage128(Wmv, sm + S_WB2, sidx);
    }
    __syncthreads();

    // ================= P9: wsum[h][i] = sum_c attn[h][c]*cluster[c][i] (ALL)
    {
        int i = t & 127, par = t >> 7;
        float acc[4] = {0.f, 0.f, 0.f, 0.f};
#pragma unroll 4
        for (int c = 0; c < CC; c++) {
            float cv = sm[S_CS + c * 129 + i];
            float4 av = *(const float4*)(sm + S_AT4 + c * 8 + par * 4);
            acc[0] = fmaf(av.x, cv, acc[0]);
            acc[1] = fmaf(av.y, cv, acc[1]);
            acc[2] = fmaf(av.z, cv, acc[2]);
            acc[3] = fmaf(av.w, cv, acc[3]);
        }
        *(float4*)(sm + S_WS4 + i * 8 + par * 4) =
            make_float4(acc[0], acc[1], acc[2], acc[3]);
    }
    __syncthreads();

    // ================= P10: y[h][j] = sum_i wsum[h][i]*Wv[i][j] (A, ALL) ===
    {
        int j = t & 127, par = t >> 7;
        float acc[4] = {0.f, 0.f, 0.f, 0.f};
#pragma unroll 4
        for (int i = 0; i < DD; i++) {
            float wvv = sm[S_WA + i * 129 + j];
            float4 sv = *(const float4*)(sm + S_WS4 + i * 8 + par * 4);
            acc[0] = fmaf(sv.x, wvv, acc[0]);
            acc[1] = fmaf(sv.y, wvv, acc[1]);
            acc[2] = fmaf(sv.z, wvv, acc[2]);
            acc[3] = fmaf(sv.w, wvv, acc[3]);
        }
#pragma unroll
        for (int m = 0; m < 4; m++) sm[S_YS + (par * 4 + m) * 132 + j] = acc[m];
    }
    __syncthreads();

    // ======= P11: gv = y @ Wmv (B, t<128)  ||  stage Wmo -> A ==============
    if (w < 4) {
        int h = t >> 4;
        float a0 = 0.f, a1 = 0.f, a2 = 0.f, a3 = 0.f;
#pragma unroll 8
        for (int j = 0; j < DD; j += 4) {
            a0 = fmaf(sm[S_YS + h * 132 + j],     sm[S_WB2 + (j)     * 129 + t], a0);
            a1 = fmaf(sm[S_YS + h * 132 + j + 1], sm[S_WB2 + (j + 1) * 129 + t], a1);
            a2 = fmaf(sm[S_YS + h * 132 + j + 2], sm[S_WB2 + (j + 2) * 129 + t], a2);
            a3 = fmaf(sm[S_YS + h * 132 + j + 3], sm[S_WB2 + (j + 3) * 129 + t], a3);
        }
        sm[S_GV + t] = (a0 + a1) + (a2 + a3);
    } else {
        stage128(Wmo, sm + S_WA, sidx);
    }
    __syncthreads();

    // ======= P12: go = gv @ Wmo (A, t<128)  ||  stage Wks -> B =============
    if (w < 4) {
        float a0 = 0.f, a1 = 0.f, a2 = 0.f, a3 = 0.f;
#pragma unroll 8
        for (int j = 0; j < DD; j += 4) {
            a0 = fmaf(sm[S_GV + j],     sm[S_WA + (j)     * 129 + t], a0);
            a1 = fmaf(sm[S_GV + j + 1], sm[S_WA + (j + 1) * 129 + t], a1);
            a2 = fmaf(sm[S_GV + j + 2], sm[S_WA + (j + 2) * 129 + t], a2);
            a3 = fmaf(sm[S_GV + j + 3], sm[S_WA + (j + 3) * 129 + t], a3);
        }
        sm[S_GO + t] = (a0 + a1) + (a2 + a3);
    } else {
        stage128(Wks, sm + S_WB2, sidx);
    }
    __syncthreads();

    // ================= P13: gw[i=t] = sum_j Wks[i][j]*go[j] (B, t<128) =====
    if (w < 4) {
        float a0 = 0.f, a1 = 0.f, a2 = 0.f, a3 = 0.f;
#pragma unroll 8
        for (int j = 0; j < DD; j += 4) {
            a0 = fmaf(sm[S_WB2 + t * 129 + j],     sm[S_GO + j],     a0);
            a1 = fmaf(sm[S_WB2 + t * 129 + j + 1], sm[S_GO + j + 1], a1);
            a2 = fmaf(sm[S_WB2 + t * 129 + j + 2], sm[S_GO + j + 2], a2);
            a3 = fmaf(sm[S_WB2 + t * 129 + j + 3], sm[S_GO + j + 3], a3);
        }
        sm[S_GW + t] = (a0 + a1) + (a2 + a3);
    }
    __syncthreads();

    // ================= P14: logits ==========================================
    if (t < 2 * CC) {
        int c = t >> 1, half = t & 1;
        float acc = 0.f;
        int i0 = half * 64;
#pragma unroll 8
        for (int i = i0; i < i0 + 64; i++)
            acc = fmaf(sm[S_CS + c * 129 + i], sm[S_GW + i], acc);
        sm[S_PART + c * 2 + half] = acc;
    }
    __syncthreads();
    if (t < CC) {
        float lg = (sm[S_PART + t * 2] + sm[S_PART + t * 2 + 1]) * 0.08838834764831845f;
        lg = tanhf(lg) * CLIPV;
        sm[S_LGT + t] = (sm[S_VCM + t] != 0.0f) ? NEGV : lg;
    }
    __syncthreads();

    // ================= P15: argmax + logsumexp (warp 0) =====================
    if (w == 0) {
        float bv = -INFINITY;
        int bi = 0x7fffffff;
        for (int c = lane; c < CC; c += 32) {
            float v = sm[S_LGT + c];
            if (v > bv || (v == bv && c < bi)) { bv = v; bi = c; }
        }
#pragma unroll
        for (int off = 16; off; off >>= 1) {
            float ov = __shfl_down_sync(0xffffffffu, bv, off);
            int oi = __shfl_down_sync(0xffffffffu, bi, off);
            if (ov > bv || (ov == bv && oi < bi)) { bv = ov; bi = oi; }
        }
        bv = __shfl_sync(0xffffffffu, bv, 0);
        bi = __shfl_sync(0xffffffffu, bi, 0);
        float s = 0.f;
        for (int c = lane; c < CC; c += 32) s += expf(sm[S_LGT + c] - bv);
#pragma unroll
        for (int off = 16; off; off >>= 1) s += __shfl_xor_sync(0xffffffffu, s, off);
        if (lane == 0) {
            sm[S_MISC + 0] = (float)bi;
            sm[S_MISC + 1] = bv + logf(s);
        }
    }
    __syncthreads();

    // ================= P16: outputs =========================================
    const int gid = (int)sm[S_MISC + 0];
    const float mlse = sm[S_MISC + 1];
    float* aug = out + OUT_AUG + (size_t)b * 512;
    float* gout = out + OUT_GEMB + (size_t)b * 128;
    float* cpo = out + OUT_CLU + (size_t)b * CC;
    if (t < DD) {
        float ge = sm[S_CS + gid * 129 + t];
        aug[t]        = isnew ? sm[S_M2 + t] : 0.0f;
        aug[128 + t]  = isnew ? sm[S_CUR + t] : 0.0f;
        aug[256 + t]  = isnew ? ge : 0.0f;
        aug[384 + t]  = isnew ? sm[S_DEP + t] : 0.0f;
        gout[t]       = isnew ? ge : 0.0f;
    }
    if (t < CC) cpo[t] = isnew ? (sm[S_LGT + t] - mlse) : 0.0f;
    if (t == 0) out[OUT_GUID + b] = isnew ? (float)gid : 0.0f;
}

extern "C" void kernel_launch(void* const* d_in, const int* in_sizes, int n_in,
                              void* d_out, int out_size) {
    (void)in_sizes; (void)n_in; (void)out_size;
    const float* depot   = (const float*)d_in[0];
    const float* cluster = (const float*)d_in[1];
    const float* curE    = (const float*)d_in[2];
    const float* node    = (const float*)d_in[3];
    const void*  isnewp  = d_in[4];
    const void*  cmaskp  = d_in[5];
    const void*  vcmp    = d_in[6];
    const void*  maskp   = d_in[7];
    const float* Wq  = (const float*)d_in[8];
    const float* Wk  = (const float*)d_in[9];
    const float* Wv  = (const float*)d_in[10];
    const float* Wks = (const float*)d_in[11];
    const float* Wmq = (const float*)d_in[12];
    const float* Wmk = (const float*)d_in[13];
    const float* Wmv = (const float*)d_in[14];
    const float* Wmo = (const float*)d_in[15];

    means_kernel<<<BB * SPLIT, 256>>>(node, maskp, cmaskp);

    cudaFuncSetAttribute(clu_fused_kernel,
                         cudaFuncAttributeMaxDynamicSharedMemorySize, SMEM_BYTES);
    clu_fused_kernel<<<BB, 256, SMEM_BYTES>>>(
        depot, cluster, curE, isnewp, vcmp, maskp,
        Wq, Wk, Wv, Wks, Wmq, Wmk, Wmv, Wmo, (float*)d_out);
}

// round 10
// speedup vs baseline: 2.7382x; 1.2856x over previous
#include <cuda_runtime.h>
#include <math.h>

// Problem constants
#define BB 128
#define NN 2000
#define CC 100
#define DD 128
#define HH 8
#define NEGV (-1000000000.0f)
#define CLIPV 10.0f

#define SPLIT 20
#define CH (NN / SPLIT)       // 100 nodes per chunk
#define PRE_CTAS 96           // weight-folding CTAs (placed first in grid)
#define FOLD_ROWS 768         // PQ:0..383  Z:384..511  ZV:512..639  ZW:640..767

// Output layout (float32, flattened tuple order)
#define OUT_AUG 0
#define OUT_GEMB 65536
#define OUT_GUID 81920
#define OUT_CLU 82048

// Global scratch
#define G2OFF (BB * SPLIT * DD)
__device__ float g_part[2 * BB * SPLIT * DD];   // partial masked sums
__device__ float g_fold[FOLD_ROWS * DD];        // folded weight products

// ---------------- Kernel 2 shared memory layout (float offsets) -------------
#define S_CS   0        // cluster tile [100][129]
#define S_WA   12900    // weight buffer A [128][129]
#define S_WB2  29412    // weight buffer B [128][129]
#define S_M1   45924
#define S_M2   46052
#define S_CUR  46180
#define S_DEP  46308
#define S_QH   46436
#define S_U4   46564    // u packed [128][8]
#define S_SCP  47588    // score partials [100][16]
#define S_AT4  49188    // attn packed [100][8]
#define S_WS4  49988    // wsum packed [128][8]
#define S_GV   51012
#define S_GW   51140
#define S_PART 51268    // [100][2] + pad
#define S_LGT  51476
#define S_MISC 51580
#define S_VCM  51584
#define SMEM_FLOATS 51688
#define SMEM_BYTES (SMEM_FLOATS * 4)

__device__ __forceinline__ bool rdmask(const void* p, int flag, long long i) {
    if (flag == 0) return ((const unsigned char*)p)[i] != 0;
    if (flag == 1) return ((const int*)p)[i] != 0;
    return ((const float*)p)[i] != 0.0f;
}

// Stage a 128x128 row-major global matrix into a [128][129] smem buffer.
// 128 threads, idx in [0,128).
__device__ __forceinline__ void stage128(const float* __restrict__ src,
                                         float* __restrict__ dst, int idx) {
#pragma unroll
    for (int k = 0; k < 32; k++) {
        int p4 = k * 128 + idx;
        float4 v = ((const float4*)src)[p4];
        int base = p4 * 4;
        float* d = dst + (base >> 7) * 129 + (base & 127);
        d[0] = v.x; d[1] = v.y; d[2] = v.z; d[3] = v.w;
    }
}

// Same with 256 threads.
__device__ __forceinline__ void stage256(const float* __restrict__ src,
                                         float* __restrict__ dst, int t) {
#pragma unroll
    for (int k = 0; k < 16; k++) {
        int p4 = k * 256 + t;
        float4 v = ((const float4*)src)[p4];
        int base = p4 * 4;
        float* d = dst + (base >> 7) * 129 + (base & 127);
        d[0] = v.x; d[1] = v.y; d[2] = v.z; d[3] = v.w;
    }
}

// ============================================================================
// Kernel 1: [blocks 0..95] weight folding  +  [blocks 96..] masked partial
// sums over node_embeddings. grid = PRE_CTAS + B*SPLIT.
// ============================================================================
__global__ void __launch_bounds__(256)
means_pre_kernel(const float* __restrict__ node, const void* __restrict__ maskp,
                 const void* __restrict__ cmaskp,
                 const float* __restrict__ Wq, const float* __restrict__ Wk,
                 const float* __restrict__ Wv, const float* __restrict__ Wks,
                 const float* __restrict__ Wmq, const float* __restrict__ Wmk,
                 const float* __restrict__ Wmv, const float* __restrict__ Wmo) {
    __shared__ float red[2 * 1024];
    __shared__ float a_sm[8 * 128];
    __shared__ unsigned char mloc[CH], cmloc[CH];
    const int t = threadIdx.x;
    const int lane = t & 31;
    const int w = t >> 5;

    // sniff bool serialization dtype (byte / int32 / float32) — all threads
    unsigned wword = ((const unsigned*)maskp)[t];
    int o1  = __syncthreads_or((wword & 0x0000ff00u) ? 1 : 0);
    int o23 = __syncthreads_or((wword & 0xffff0000u) ? 1 : 0);
    const int flag = o1 ? 0 : (o23 ? 2 : 1);

    if (blockIdx.x < PRE_CTAS) {
        // -------- weight folding: 8 output rows of the 768-row table --------
        const int r0 = blockIdx.x * 8;
        // stage the 8 A-rows (coalesced)
        for (int idx = t; idx < 8 * 128; idx += 256) {
            int row = idx >> 7, j = idx & 127;
            int R = r0 + row;
            const float* A;
            if (R < 384)      A = Wq  + (size_t)R * DD;
            else if (R < 512) A = Wk  + (size_t)(R - 384) * DD;
            else if (R < 640) A = Wv  + (size_t)(R - 512) * DD;
            else              A = Wmo + (size_t)(R - 640) * DD;
            a_sm[idx] = A[j];
        }
        __syncthreads();
        const int col = t & 127, rr = t >> 7;
        float a0 = 0.f, a1 = 0.f, a2 = 0.f, a3 = 0.f;
        if (r0 < 640) {
            const float* Bm = (r0 < 384) ? Wmq : (r0 < 512) ? Wmk : Wmv;
#pragma unroll 8
            for (int j = 0; j < DD; j++) {
                float bv = Bm[j * DD + col];
                a0 = fmaf(a_sm[(rr + 0) * DD + j], bv, a0);
                a1 = fmaf(a_sm[(rr + 2) * DD + j], bv, a1);
                a2 = fmaf(a_sm[(rr + 4) * DD + j], bv, a2);
                a3 = fmaf(a_sm[(rr + 6) * DD + j], bv, a3);
            }
        } else {
            // ZW[m][i] = sum_j Wmo[m][j] * Wks[i][j]; col = i
#pragma unroll 4
            for (int j = 0; j < DD; j += 4) {
                float4 wv = *(const float4*)(Wks + (size_t)col * DD + j);
                a0 = fmaf(a_sm[(rr + 0) * DD + j],     wv.x, a0);
                a0 = fmaf(a_sm[(rr + 0) * DD + j + 1], wv.y, a0);
                a0 = fmaf(a_sm[(rr + 0) * DD + j + 2], wv.z, a0);
                a0 = fmaf(a_sm[(rr + 0) * DD + j + 3], wv.w, a0);
                a1 = fmaf(a_sm[(rr + 2) * DD + j],     wv.x, a1);
                a1 = fmaf(a_sm[(rr + 2) * DD + j + 1], wv.y, a1);
                a1 = fmaf(a_sm[(rr + 2) * DD + j + 2], wv.z, a1);
                a1 = fmaf(a_sm[(rr + 2) * DD + j + 3], wv.w, a1);
                a2 = fmaf(a_sm[(rr + 4) * DD + j],     wv.x, a2);
                a2 = fmaf(a_sm[(rr + 4) * DD + j + 1], wv.y, a2);
                a2 = fmaf(a_sm[(rr + 4) * DD + j + 2], wv.z, a2);
                a2 = fmaf(a_sm[(rr + 4) * DD + j + 3], wv.w, a2);
                a3 = fmaf(a_sm[(rr + 6) * DD + j],     wv.x, a3);
                a3 = fmaf(a_sm[(rr + 6) * DD + j + 1], wv.y, a3);
                a3 = fmaf(a_sm[(rr + 6) * DD + j + 2], wv.z, a3);
                a3 = fmaf(a_sm[(rr + 6) * DD + j + 3], wv.w, a3);
            }
        }
        g_fold[(size_t)(r0 + rr + 0) * DD + col] = a0;
        g_fold[(size_t)(r0 + rr + 2) * DD + col] = a1;
        g_fold[(size_t)(r0 + rr + 4) * DD + col] = a2;
        g_fold[(size_t)(r0 + rr + 6) * DD + col] = a3;
        return;
    }

    // ---------------- means path ----------------
    const int bs = blockIdx.x - PRE_CTAS;
    const int b = bs / SPLIT;
    const int s = bs % SPLIT;

    const long long mbase = (long long)b * NN + s * CH;
    for (int n = t; n < CH; n += 256) {
        mloc[n]  = rdmask(maskp,  flag, mbase + n) ? 1 : 0;
        cmloc[n] = rdmask(cmaskp, flag, mbase + n) ? 1 : 0;
    }
    __syncthreads();

    const float* np_ = node + ((size_t)b * NN + (size_t)s * CH) * DD;
    const int d0 = lane * 4;
    float4 a1 = make_float4(0.f, 0.f, 0.f, 0.f);
    float4 a2 = make_float4(0.f, 0.f, 0.f, 0.f);
#pragma unroll 6
    for (int n = w; n < CH; n += 8) {
        float4 v = __ldcs((const float4*)(np_ + (size_t)n * DD + d0));
        bool m = mloc[n] != 0;
        bool mc = (mloc[n] | cmloc[n]) != 0;
        if (!m)  { a1.x += v.x; a1.y += v.y; a1.z += v.z; a1.w += v.w; }
        if (!mc) { a2.x += v.x; a2.y += v.y; a2.z += v.z; a2.w += v.w; }
    }
    int o = w * 128 + d0;
    red[o] = a1.x; red[o + 1] = a1.y; red[o + 2] = a1.z; red[o + 3] = a1.w;
    red[1024 + o] = a2.x; red[1024 + o + 1] = a2.y;
    red[1024 + o + 2] = a2.z; red[1024 + o + 3] = a2.w;
    __syncthreads();
    if (t < DD) {
        float s1 = 0.f, s2 = 0.f;
#pragma unroll
        for (int ww = 0; ww < 8; ww++) {
            s1 += red[ww * 128 + t];
            s2 += red[1024 + ww * 128 + t];
        }
        size_t idx = (size_t)(b * SPLIT + s) * DD + t;
        g_part[idx] = s1;
        g_part[G2OFF + idx] = s2;
    }
}

// ============================================================================
// Kernel 2: per-batch fused compute with folded weights. grid = B, block 256.
// ============================================================================
__global__ void __launch_bounds__(256, 1)
clu_fused_kernel(const float* __restrict__ depot, const float* __restrict__ cluster,
                 const float* __restrict__ curE,
                 const void* __restrict__ isnewp,
                 const void* __restrict__ vcmp, const void* __restrict__ maskp,
                 float* __restrict__ out) {
    extern __shared__ float sm[];
    const int b = blockIdx.x;
    const int t = threadIdx.x;
    const int lane = t & 31;
    const int w = t >> 5;
    const int sidx = t - 128;

    // sniff bool dtype
    unsigned wword = ((const unsigned*)maskp)[t];
    int o1  = __syncthreads_or((wword & 0x0000ff00u) ? 1 : 0);
    int o23 = __syncthreads_or((wword & 0xffff0000u) ? 1 : 0);
    const int flag = o1 ? 0 : (o23 ? 2 : 1);
    const bool isnew = rdmask(isnewp, flag, b);

    // ===== P0: loads + means reduce + stage PQ0 -> A ========================
    if (t < DD) {
        sm[S_CUR + t] = curE[b * DD + t];
        sm[S_DEP + t] = depot[b * DD + t];
    }
    if (t < CC) sm[S_VCM + t] = rdmask(vcmp, flag, (long long)b * CC + t) ? 1.0f : 0.0f;
    {
        const float* cp = cluster + (size_t)b * CC * DD;
#pragma unroll
        for (int p4 = t; p4 < (CC * DD) / 4; p4 += 256) {
            float4 v = ((const float4*)cp)[p4];
            int base = p4 * 4;
            float* dst = sm + S_CS + (base >> 7) * 129 + (base & 127);
            dst[0] = v.x; dst[1] = v.y; dst[2] = v.z; dst[3] = v.w;
        }
    }
    if (t < DD) {
        float s1 = 0.f, s2 = 0.f;
#pragma unroll
        for (int s = 0; s < SPLIT; s++) {
            size_t idx = (size_t)(b * SPLIT + s) * DD + t;
            s1 += g_part[idx];
            s2 += g_part[G2OFF + idx];
        }
        sm[S_M1 + t] = s1 * (1.0f / NN);
        sm[S_M2 + t] = s2 * (1.0f / NN);
    }
    stage256(g_fold, sm + S_WA, t);          // PQ0
    __syncthreads();

    float qa = 0.f;

    // ===== P1: qa += m1 @ PQ0 (A)  ||  stage PQ1 -> B =======================
    if (w < 4) {
        float a0 = 0.f, a1 = 0.f, a2 = 0.f, a3 = 0.f;
#pragma unroll 8
        for (int i = 0; i < DD; i += 4) {
            a0 = fmaf(sm[S_M1 + i],     sm[S_WA + (i)     * 129 + t], a0);
            a1 = fmaf(sm[S_M1 + i + 1], sm[S_WA + (i + 1) * 129 + t], a1);
            a2 = fmaf(sm[S_M1 + i + 2], sm[S_WA + (i + 2) * 129 + t], a2);
            a3 = fmaf(sm[S_M1 + i + 3], sm[S_WA + (i + 3) * 129 + t], a3);
        }
        qa += (a0 + a1) + (a2 + a3);
    } else {
        stage128(g_fold + DD * DD, sm + S_WB2, sidx);   // PQ1
        if (w == 4) {
            bool ok = true;
            for (int c = 1 + lane; c < CC; c += 32) ok = ok && (sm[S_VCM + c] != 0.0f);
            bool allv = __all_sync(0xffffffffu, ok);
            if (lane == 0 && isnew) sm[S_VCM + 0] = allv ? 0.0f : 1.0f;
        }
    }
    __syncthreads();

    // ===== P2: qa += cur @ PQ1 (B)  ||  stage PQ2 -> A ======================
    if (w < 4) {
        float a0 = 0.f, a1 = 0.f, a2 = 0.f, a3 = 0.f;
#pragma unroll 8
        for (int i = 0; i < DD; i += 4) {
            a0 = fmaf(sm[S_CUR + i],     sm[S_WB2 + (i)     * 129 + t], a0);
            a1 = fmaf(sm[S_CUR + i + 1], sm[S_WB2 + (i + 1) * 129 + t], a1);
            a2 = fmaf(sm[S_CUR + i + 2], sm[S_WB2 + (i + 2) * 129 + t], a2);
            a3 = fmaf(sm[S_CUR + i + 3], sm[S_WB2 + (i + 3) * 129 + t], a3);
        }
        qa += (a0 + a1) + (a2 + a3);
    } else {
        stage128(g_fold + 2 * DD * DD, sm + S_WA, sidx);   // PQ2
    }
    __syncthreads();

    // ===== P3: qh = qa + dep @ PQ2 (A)  ||  stage Z -> B ====================
    if (w < 4) {
        float a0 = 0.f, a1 = 0.f, a2 = 0.f, a3 = 0.f;
#pragma unroll 8
        for (int i = 0; i < DD; i += 4) {
            a0 = fmaf(sm[S_DEP + i],     sm[S_WA + (i)     * 129 + t], a0);
            a1 = fmaf(sm[S_DEP + i + 1], sm[S_WA + (i + 1) * 129 + t], a1);
            a2 = fmaf(sm[S_DEP + i + 2], sm[S_WA + (i + 2) * 129 + t], a2);
            a3 = fmaf(sm[S_DEP + i + 3], sm[S_WA + (i + 3) * 129 + t], a3);
        }
        qa += (a0 + a1) + (a2 + a3);
        sm[S_QH + t] = qa;
    } else {
        stage128(g_fold + 384 * DD, sm + S_WB2, sidx);   // Z
    }
    __syncthreads();

    // ===== P4: u[h][i=t] = sum_k Z[i][16h+k]*qh[16h+k] (B)  || stage ZV -> A
    if (w < 4) {
#pragma unroll
        for (int h = 0; h < HH; h++) {
            float a = 0.f;
#pragma unroll
            for (int k = 0; k < 16; k++)
                a = fmaf(sm[S_WB2 + t * 129 + 16 * h + k], sm[S_QH + 16 * h + k], a);
            sm[S_U4 + t * 8 + h] = a;
        }
    } else {
        stage128(g_fold + 512 * DD, sm + S_WA, sidx);    // ZV
    }
    __syncthreads();

    // ===== P5: score partials (t<200: c, half) ==============================
    if (t < 2 * CC) {
        int c = t >> 1, half = t & 1, i0 = half * 64;
        float acc[8] = {0.f, 0.f, 0.f, 0.f, 0.f, 0.f, 0.f, 0.f};
#pragma unroll 4
        for (int i = i0; i < i0 + 64; i++) {
            float cv = sm[S_CS + c * 129 + i];
            float4 u0 = *(const float4*)(sm + S_U4 + i * 8);
            float4 u1 = *(const float4*)(sm + S_U4 + i * 8 + 4);
            acc[0] = fmaf(cv, u0.x, acc[0]);
            acc[1] = fmaf(cv, u0.y, acc[1]);
            acc[2] = fmaf(cv, u0.z, acc[2]);
            acc[3] = fmaf(cv, u0.w, acc[3]);
            acc[4] = fmaf(cv, u1.x, acc[4]);
            acc[5] = fmaf(cv, u1.y, acc[5]);
            acc[6] = fmaf(cv, u1.z, acc[6]);
            acc[7] = fmaf(cv, u1.w, acc[7]);
        }
#pragma unroll
        for (int h = 0; h < HH; h++) sm[S_SCP + c * 16 + half * 8 + h] = acc[h];
    }
    __syncthreads();

    // ===== P6: softmax (warps 0-3, 2 heads each)  ||  stage ZW -> B =========
    if (w < 4) {
#pragma unroll
        for (int hh = 0; hh < 2; hh++) {
            int h = w + hh * 4;
            float vv[4];
            float mx = -INFINITY;
#pragma unroll
            for (int idx = 0; idx < 4; idx++) {
                int c = lane + 32 * idx;
                float val = -INFINITY;
                if (c < CC) {
                    float scv = sm[S_SCP + c * 16 + h] + sm[S_SCP + c * 16 + 8 + h];
                    val = (sm[S_VCM + c] != 0.0f) ? NEGV : scv * 0.25f;
                }
                vv[idx] = val;
                mx = fmaxf(mx, val);
            }
#pragma unroll
            for (int off = 16; off; off >>= 1)
                mx = fmaxf(mx, __shfl_xor_sync(0xffffffffu, mx, off));
            float ssum = 0.f;
#pragma unroll
            for (int idx = 0; idx < 4; idx++) {
                int c = lane + 32 * idx;
                if (c < CC) {
                    float e = expf(vv[idx] - mx);
                    ssum += e;
                    vv[idx] = e;
                }
            }
#pragma unroll
            for (int off = 16; off; off >>= 1)
                ssum += __shfl_xor_sync(0xffffffffu, ssum, off);
            float inv = 1.0f / ssum;
#pragma unroll
            for (int idx = 0; idx < 4; idx++) {
                int c = lane + 32 * idx;
                if (c < CC) sm[S_AT4 + c * 8 + h] = vv[idx] * inv;
            }
        }
    } else {
        stage128(g_fold + 640 * DD, sm + S_WB2, sidx);   // ZW
    }
    __syncthreads();

    // ===== P7: wsum[h][i] = sum_c attn[h][c]*cluster[c][i] (ALL 256) ========
    {
        int i = t & 127, par = t >> 7;
        float acc[4] = {0.f, 0.f, 0.f, 0.f};
#pragma unroll 4
        for (int c = 0; c < CC; c++) {
            float cv = sm[S_CS + c * 129 + i];
            float4 av = *(const float4*)(sm + S_AT4 + c * 8 + par * 4);
            acc[0] = fmaf(av.x, cv, acc[0]);
            acc[1] = fmaf(av.y, cv, acc[1]);
            acc[2] = fmaf(av.z, cv, acc[2]);
            acc[3] = fmaf(av.w, cv, acc[3]);
        }
        *(float4*)(sm + S_WS4 + i * 8 + par * 4) =
            make_float4(acc[0], acc[1], acc[2], acc[3]);
    }
    __syncthreads();

    // ===== P8: gv[m=t] = sum_i wsum[h(m)][i]*ZV[i][m] (A, t<128) ============
    if (w < 4) {
        int h = t >> 4;
        float a0 = 0.f, a1 = 0.f, a2 = 0.f, a3 = 0.f;
#pragma unroll 8
        for (int i = 0; i < DD; i += 4) {
            a0 = fmaf(sm[S_WS4 + (i + 0) * 8 + h], sm[S_WA + (i + 0) * 129 + t], a0);
            a1 = fmaf(sm[S_WS4 + (i + 1) * 8 + h], sm[S_WA + (i + 1) * 129 + t], a1);
            a2 = fmaf(sm[S_WS4 + (i + 2) * 8 + h], sm[S_WA + (i + 2) * 129 + t], a2);
            a3 = fmaf(sm[S_WS4 + (i + 3) * 8 + h], sm[S_WA + (i + 3) * 129 + t], a3);
        }
        sm[S_GV + t] = (a0 + a1) + (a2 + a3);
    }
    __syncthreads();

    // ===== P9: gw[i=t] = sum_m gv[m]*ZW[m][i] (B, t<128) ====================
    if (w < 4) {
        float a0 = 0.f, a1 = 0.f, a2 = 0.f, a3 = 0.f;
#pragma unroll 8
        for (int m = 0; m < DD; m += 4) {
            a0 = fmaf(sm[S_GV + m],     sm[S_WB2 + (m)     * 129 + t], a0);
            a1 = fmaf(sm[S_GV + m + 1], sm[S_WB2 + (m + 1) * 129 + t], a1);
            a2 = fmaf(sm[S_GV + m + 2], sm[S_WB2 + (m + 2) * 129 + t], a2);
            a3 = fmaf(sm[S_GV + m + 3], sm[S_WB2 + (m + 3) * 129 + t], a3);
        }
        sm[S_GW + t] = (a0 + a1) + (a2 + a3);
    }
    __syncthreads();

    // ===== P10: logit partials (t<200) ======================================
    if (t < 2 * CC) {
        int c = t >> 1, half = t & 1;
        float acc = 0.f;
        int i0 = half * 64;
#pragma unroll 8
        for (int i = i0; i < i0 + 64; i++)
            acc = fmaf(sm[S_CS + c * 129 + i], sm[S_GW + i], acc);
        sm[S_PART + c * 2 + half] = acc;
    }
    __syncthreads();
    if (t < CC) {
        float lg = (sm[S_PART + t * 2] + sm[S_PART + t * 2 + 1]) * 0.08838834764831845f;
        lg = tanhf(lg) * CLIPV;
        sm[S_LGT + t] = (sm[S_VCM + t] != 0.0f) ? NEGV : lg;
    }
    __syncthreads();

    // ===== P12: argmax + logsumexp (warp 0) =================================
    if (w == 0) {
        float bv = -INFINITY;
        int bi = 0x7fffffff;
        for (int c = lane; c < CC; c += 32) {
            float v = sm[S_LGT + c];
            if (v > bv || (v == bv && c < bi)) { bv = v; bi = c; }
        }
#pragma unroll
        for (int off = 16; off; off >>= 1) {
            float ov = __shfl_down_sync(0xffffffffu, bv, off);
            int oi = __shfl_down_sync(0xffffffffu, bi, off);
            if (ov > bv || (ov == bv && oi < bi)) { bv = ov; bi = oi; }
        }
        bv = __shfl_sync(0xffffffffu, bv, 0);
        bi = __shfl_sync(0xffffffffu, bi, 0);
        float s = 0.f;
        for (int c = lane; c < CC; c += 32) s += expf(sm[S_LGT + c] - bv);
#pragma unroll
        for (int off = 16; off; off >>= 1) s += __shfl_xor_sync(0xffffffffu, s, off);
        if (lane == 0) {
            sm[S_MISC + 0] = (float)bi;
            sm[S_MISC + 1] = bv + logf(s);
        }
    }
    __syncthreads();

    // ===== P13: outputs =====================================================
    const int gid = (int)sm[S_MISC + 0];
    const float mlse = sm[S_MISC + 1];
    float* aug = out + OUT_AUG + (size_t)b * 512;
    float* gout = out + OUT_GEMB + (size_t)b * 128;
    float* cpo = out + OUT_CLU + (size_t)b * CC;
    if (t < DD) {
        float ge = sm[S_CS + gid * 129 + t];
        aug[t]        = isnew ? sm[S_M2 + t] : 0.0f;
        aug[128 + t]  = isnew ? sm[S_CUR + t] : 0.0f;
        aug[256 + t]  = isnew ? ge : 0.0f;
        aug[384 + t]  = isnew ? sm[S_DEP + t] : 0.0f;
        gout[t]       = isnew ? ge : 0.0f;
    }
    if (t < CC) cpo[t] = isnew ? (sm[S_LGT + t] - mlse) : 0.0f;
    if (t == 0) out[OUT_GUID + b] = isnew ? (float)gid : 0.0f;
}

extern "C" void kernel_launch(void* const* d_in, const int* in_sizes, int n_in,
                              void* d_out, int out_size) {
    (void)in_sizes; (void)n_in; (void)out_size;
    const float* depot   = (const float*)d_in[0];
    const float* cluster = (const float*)d_in[1];
    const float* curE    = (const float*)d_in[2];
    const float* node    = (const float*)d_in[3];
    const void*  isnewp  = d_in[4];
    const void*  cmaskp  = d_in[5];
    const void*  vcmp    = d_in[6];
    const void*  maskp   = d_in[7];
    const float* Wq  = (const float*)d_in[8];
    const float* Wk  = (const float*)d_in[9];
    const float* Wv  = (const float*)d_in[10];
    const float* Wks = (const float*)d_in[11];
    const float* Wmq = (const float*)d_in[12];
    const float* Wmk = (const float*)d_in[13];
    const float* Wmv = (const float*)d_in[14];
    const float* Wmo = (const float*)d_in[15];

    means_pre_kernel<<<PRE_CTAS + BB * SPLIT, 256>>>(
        node, maskp, cmaskp, Wq, Wk, Wv, Wks, Wmq, Wmk, Wmv, Wmo);

    cudaFuncSetAttribute(clu_fused_kernel,
                         cudaFuncAttributeMaxDynamicSharedMemorySize, SMEM_BYTES);
    clu_fused_kernel<<<BB, 256, SMEM_BYTES>>>(
        depot, cluster, curE, isnewp, vcmp, maskp, (float*)d_out);
}

// round 11
// speedup vs baseline: 3.2569x; 1.1894x over previous
#include <cuda_runtime.h>
#include <math.h>

// Problem constants
#define BB 128
#define NN 2000
#define CC 100
#define DD 128
#define HH 8
#define NEGV (-1000000000.0f)
#define CLIPV 10.0f

#define SPLIT 20
#define CH (NN / SPLIT)       // 100 nodes per chunk
#define PRE_CTAS 96           // weight-folding CTAs (placed first in grid)
#define FOLD_ROWS 768         // PQ:0..383  Zt:384..511  ZV:512..639  ZW:640..767

// Output layout (float32, flattened tuple order)
#define OUT_AUG 0
#define OUT_GEMB 65536
#define OUT_GUID 81920
#define OUT_CLU 82048

// Global scratch
#define G2OFF (BB * SPLIT * DD)
__device__ float g_part[2 * BB * SPLIT * DD];   // partial masked sums
__device__ float g_fold[FOLD_ROWS * DD];        // folded weight products

// ---------------- Kernel 2 shared memory layout (float offsets) -------------
#define S_CS   0        // cluster tile [100][129]
#define S_PB   12900    // warp partials [16][132]
#define S_M1   15012
#define S_M2   15140
#define S_CUR  15268
#define S_DEP  15396
#define S_CTX  15524    // [384]
#define S_QH   15908
#define S_U4   16036    // u packed [128][8]
#define S_SCP  17060    // score partials [100][16]
#define S_AT4  18660    // attn packed [100][8]
#define S_WS4  19460    // wsum packed [128][8]
#define S_GV   20484
#define S_GW   20612
#define S_PART 20740    // [100][2] + pad
#define S_LGT  20948
#define S_MISC 21052
#define S_VCM  21056
#define SMEM_FLOATS 21160
#define SMEM_BYTES (SMEM_FLOATS * 4)

__device__ __forceinline__ bool rdmask(const void* p, int flag, long long i) {
    if (flag == 0) return ((const unsigned char*)p)[i] != 0;
    if (flag == 1) return ((const int*)p)[i] != 0;
    return ((const float*)p)[i] != 0.0f;
}

// ============================================================================
// Kernel 1: [blocks 0..95] weight folding  +  [blocks 96..] masked partial
// sums over node_embeddings. grid = PRE_CTAS + B*SPLIT.
// ============================================================================
__global__ void __launch_bounds__(256)
means_pre_kernel(const float* __restrict__ node, const void* __restrict__ maskp,
                 const void* __restrict__ cmaskp,
                 const float* __restrict__ Wq, const float* __restrict__ Wk,
                 const float* __restrict__ Wv, const float* __restrict__ Wks,
                 const float* __restrict__ Wmq, const float* __restrict__ Wmk,
                 const float* __restrict__ Wmv, const float* __restrict__ Wmo) {
    __shared__ float red[2 * 1024];
    __shared__ float a_sm[8 * 128];
    __shared__ unsigned char mloc[CH], cmloc[CH];
    const int t = threadIdx.x;
    const int lane = t & 31;
    const int w = t >> 5;

    // sniff bool serialization dtype (byte / int32 / float32)
    unsigned wword = ((const unsigned*)maskp)[t];
    int o1  = __syncthreads_or((wword & 0x0000ff00u) ? 1 : 0);
    int o23 = __syncthreads_or((wword & 0xffff0000u) ? 1 : 0);
    const int flag = o1 ? 0 : (o23 ? 2 : 1);

    if (blockIdx.x < PRE_CTAS) {
        // -------- weight folding: 8 output rows of the 768-row table --------
        const int r0 = blockIdx.x * 8;
        for (int idx = t; idx < 8 * 128; idx += 256) {
            int row = idx >> 7, j = idx & 127;
            int R = r0 + row;
            const float* A;
            if (R < 384)      A = Wq  + (size_t)R * DD;
            else if (R < 512) A = Wk  + (size_t)(R - 384) * DD;
            else if (R < 640) A = Wv  + (size_t)(R - 512) * DD;
            else              A = Wmo + (size_t)(R - 640) * DD;
            a_sm[idx] = A[j];
        }
        __syncthreads();
        const int col = t & 127, rr = t >> 7;
        float a0 = 0.f, a1 = 0.f, a2 = 0.f, a3 = 0.f;
        if (r0 < 640) {
            const float* Bm = (r0 < 384) ? Wmq : (r0 < 512) ? Wmk : Wmv;
#pragma unroll 8
            for (int j = 0; j < DD; j++) {
                float bv = Bm[j * DD + col];
                a0 = fmaf(a_sm[(rr + 0) * DD + j], bv, a0);
                a1 = fmaf(a_sm[(rr + 2) * DD + j], bv, a1);
                a2 = fmaf(a_sm[(rr + 4) * DD + j], bv, a2);
                a3 = fmaf(a_sm[(rr + 6) * DD + j], bv, a3);
            }
        } else {
            // ZW[m][i] = sum_j Wmo[m][j] * Wks[i][j]; col = i
#pragma unroll 4
            for (int j = 0; j < DD; j += 4) {
                float4 wv = *(const float4*)(Wks + (size_t)col * DD + j);
                a0 = fmaf(a_sm[(rr + 0) * DD + j],     wv.x, a0);
                a0 = fmaf(a_sm[(rr + 0) * DD + j + 1], wv.y, a0);
                a0 = fmaf(a_sm[(rr + 0) * DD + j + 2], wv.z, a0);
                a0 = fmaf(a_sm[(rr + 0) * DD + j + 3], wv.w, a0);
                a1 = fmaf(a_sm[(rr + 2) * DD + j],     wv.x, a1);
                a1 = fmaf(a_sm[(rr + 2) * DD + j + 1], wv.y, a1);
                a1 = fmaf(a_sm[(rr + 2) * DD + j + 2], wv.z, a1);
                a1 = fmaf(a_sm[(rr + 2) * DD + j + 3], wv.w, a1);
                a2 = fmaf(a_sm[(rr + 4) * DD + j],     wv.x, a2);
                a2 = fmaf(a_sm[(rr + 4) * DD + j + 1], wv.y, a2);
                a2 = fmaf(a_sm[(rr + 4) * DD + j + 2], wv.z, a2);
                a2 = fmaf(a_sm[(rr + 4) * DD + j + 3], wv.w, a2);
                a3 = fmaf(a_sm[(rr + 6) * DD + j],     wv.x, a3);
                a3 = fmaf(a_sm[(rr + 6) * DD + j + 1], wv.y, a3);
                a3 = fmaf(a_sm[(rr + 6) * DD + j + 2], wv.z, a3);
                a3 = fmaf(a_sm[(rr + 6) * DD + j + 3], wv.w, a3);
            }
        }
        if (r0 >= 384 && r0 < 512) {
            // Z region: store TRANSPOSED (Zt[k][i]); k = col, i = output row
            int ib = r0 - 384 + rr;
            float* zt = g_fold + (size_t)(384 + col) * DD;
            zt[ib + 0] = a0;
            zt[ib + 2] = a1;
            zt[ib + 4] = a2;
            zt[ib + 6] = a3;
        } else {
            g_fold[(size_t)(r0 + rr + 0) * DD + col] = a0;
            g_fold[(size_t)(r0 + rr + 2) * DD + col] = a1;
            g_fold[(size_t)(r0 + rr + 4) * DD + col] = a2;
            g_fold[(size_t)(r0 + rr + 6) * DD + col] = a3;
        }
        return;
    }

    // ---------------- means path ----------------
    const int bs = blockIdx.x - PRE_CTAS;
    const int b = bs / SPLIT;
    const int s = bs % SPLIT;

    const long long mbase = (long long)b * NN + s * CH;
    for (int n = t; n < CH; n += 256) {
        mloc[n]  = rdmask(maskp,  flag, mbase + n) ? 1 : 0;
        cmloc[n] = rdmask(cmaskp, flag, mbase + n) ? 1 : 0;
    }
    __syncthreads();

    const float* np_ = node + ((size_t)b * NN + (size_t)s * CH) * DD;
    const int d0 = lane * 4;
    float4 a1 = make_float4(0.f, 0.f, 0.f, 0.f);
    float4 a2 = make_float4(0.f, 0.f, 0.f, 0.f);
#pragma unroll 6
    for (int n = w; n < CH; n += 8) {
        float4 v = __ldcs((const float4*)(np_ + (size_t)n * DD + d0));
        bool m = mloc[n] != 0;
        bool mc = (mloc[n] | cmloc[n]) != 0;
        if (!m)  { a1.x += v.x; a1.y += v.y; a1.z += v.z; a1.w += v.w; }
        if (!mc) { a2.x += v.x; a2.y += v.y; a2.z += v.z; a2.w += v.w; }
    }
    int o = w * 128 + d0;
    red[o] = a1.x; red[o + 1] = a1.y; red[o + 2] = a1.z; red[o + 3] = a1.w;
    red[1024 + o] = a2.x; red[1024 + o + 1] = a2.y;
    red[1024 + o + 2] = a2.z; red[1024 + o + 3] = a2.w;
    __syncthreads();
    if (t < DD) {
        float s1 = 0.f, s2 = 0.f;
#pragma unroll
        for (int ww = 0; ww < 8; ww++) {
            s1 += red[ww * 128 + t];
            s2 += red[1024 + ww * 128 + t];
        }
        size_t idx = (size_t)(b * SPLIT + s) * DD + t;
        g_part[idx] = s1;
        g_part[G2OFF + idx] = s2;
    }
}

// ============================================================================
// Kernel 2: per-batch fused compute. Outer-product matvecs read folded
// weights directly from L2 (no smem staging). grid = B, block = 512.
// ============================================================================
__global__ void __launch_bounds__(512, 1)
clu_fused_kernel(const float* __restrict__ depot, const float* __restrict__ cluster,
                 const float* __restrict__ curE,
                 const void* __restrict__ isnewp,
                 const void* __restrict__ vcmp, const void* __restrict__ maskp,
                 float* __restrict__ out) {
    extern __shared__ float sm[];
    const int b = blockIdx.x;
    const int t = threadIdx.x;
    const int lane = t & 31;
    const int w = t >> 5;
    const int c4 = lane * 4;

    // sniff bool dtype
    unsigned wword = ((const unsigned*)maskp)[t];
    int o1  = __syncthreads_or((wword & 0x0000ff00u) ? 1 : 0);
    int o23 = __syncthreads_or((wword & 0xffff0000u) ? 1 : 0);
    const int flag = o1 ? 0 : (o23 ? 2 : 1);
    const bool isnew = rdmask(isnewp, flag, b);

    // ===== P0: loads, means reduce, ctx build ==============================
    if (t < DD) {
        sm[S_CUR + t] = curE[b * DD + t];
        sm[S_DEP + t] = depot[b * DD + t];
    }
    if (t < CC) sm[S_VCM + t] = rdmask(vcmp, flag, (long long)b * CC + t) ? 1.0f : 0.0f;
    {
        const float* cp = cluster + (size_t)b * CC * DD;
        for (int p4 = t; p4 < (CC * DD) / 4; p4 += 512) {
            float4 v = ((const float4*)cp)[p4];
            int base = p4 * 4;
            float* dst = sm + S_CS + (base >> 7) * 129 + (base & 127);
            dst[0] = v.x; dst[1] = v.y; dst[2] = v.z; dst[3] = v.w;
        }
    }
    if (t < DD) {
        float s1 = 0.f, s2 = 0.f;
#pragma unroll
        for (int s = 0; s < SPLIT; s++) {
            size_t idx = (size_t)(b * SPLIT + s) * DD + t;
            s1 += g_part[idx];
            s2 += g_part[G2OFF + idx];
        }
        float m1 = s1 * (1.0f / NN);
        sm[S_M1 + t] = m1;
        sm[S_M2 + t] = s2 * (1.0f / NN);
        sm[S_CTX + t] = m1;
        sm[S_CTX + 128 + t] = sm[S_CUR + t];
        sm[S_CTX + 256 + t] = sm[S_DEP + t];
    }
    __syncthreads();

    // ===== P1: qh partials — warp w takes 24 rows of PQ =====================
    {
        float4 acc = make_float4(0.f, 0.f, 0.f, 0.f);
        int r0 = w * 24;
#pragma unroll 6
        for (int r = r0; r < r0 + 24; r++) {
            float4 pv = *(const float4*)(g_fold + (size_t)r * DD + c4);
            float cx = sm[S_CTX + r];
            acc.x = fmaf(cx, pv.x, acc.x);
            acc.y = fmaf(cx, pv.y, acc.y);
            acc.z = fmaf(cx, pv.z, acc.z);
            acc.w = fmaf(cx, pv.w, acc.w);
        }
        *(float4*)(sm + S_PB + w * 132 + c4) = acc;
        if (w == 15) {  // vcm[0] adjustment
            bool ok = true;
            for (int c = 1 + lane; c < CC; c += 32) ok = ok && (sm[S_VCM + c] != 0.0f);
            bool allv = __all_sync(0xffffffffu, ok);
            if (lane == 0 && isnew) sm[S_VCM + 0] = allv ? 0.0f : 1.0f;
        }
    }
    __syncthreads();

    // ===== P2: qh reduce =====================================================
    if (t < DD) {
        float s = 0.f;
#pragma unroll
        for (int ww = 0; ww < 16; ww++) s += sm[S_PB + ww * 132 + t];
        sm[S_QH + t] = s;
    }
    __syncthreads();

    // ===== P3: u[i][h] — warp w = head w, 16 rows of Zt ======================
    if (w < 8) {
        const float* Zt = g_fold + 384 * DD;
        float4 acc = make_float4(0.f, 0.f, 0.f, 0.f);
#pragma unroll
        for (int k = 0; k < 16; k++) {
            float4 zv = *(const float4*)(Zt + (size_t)(16 * w + k) * DD + c4);
            float q = sm[S_QH + 16 * w + k];
            acc.x = fmaf(q, zv.x, acc.x);
            acc.y = fmaf(q, zv.y, acc.y);
            acc.z = fmaf(q, zv.z, acc.z);
            acc.w = fmaf(q, zv.w, acc.w);
        }
        sm[S_U4 + (c4 + 0) * 8 + w] = acc.x;
        sm[S_U4 + (c4 + 1) * 8 + w] = acc.y;
        sm[S_U4 + (c4 + 2) * 8 + w] = acc.z;
        sm[S_U4 + (c4 + 3) * 8 + w] = acc.w;
    }
    __syncthreads();

    // ===== P4: score partials (t<200: c, half) ===============================
    if (t < 2 * CC) {
        int c = t >> 1, half = t & 1, i0 = half * 64;
        float acc[8] = {0.f, 0.f, 0.f, 0.f, 0.f, 0.f, 0.f, 0.f};
#pragma unroll 4
        for (int i = i0; i < i0 + 64; i++) {
            float cv = sm[S_CS + c * 129 + i];
            float4 u0 = *(const float4*)(sm + S_U4 + i * 8);
            float4 u1 = *(const float4*)(sm + S_U4 + i * 8 + 4);
            acc[0] = fmaf(cv, u0.x, acc[0]);
            acc[1] = fmaf(cv, u0.y, acc[1]);
            acc[2] = fmaf(cv, u0.z, acc[2]);
            acc[3] = fmaf(cv, u0.w, acc[3]);
            acc[4] = fmaf(cv, u1.x, acc[4]);
            acc[5] = fmaf(cv, u1.y, acc[5]);
            acc[6] = fmaf(cv, u1.z, acc[6]);
            acc[7] = fmaf(cv, u1.w, acc[7]);
        }
#pragma unroll
        for (int h = 0; h < HH; h++) sm[S_SCP + c * 16 + half * 8 + h] = acc[h];
    }
    __syncthreads();

    // ===== P5: softmax — warp w (<8) handles head h=w ========================
    if (w < 8) {
        int h = w;
        float vv[4];
        float mx = -INFINITY;
#pragma unroll
        for (int idx = 0; idx < 4; idx++) {
            int c = lane + 32 * idx;
            float val = -INFINITY;
            if (c < CC) {
                float scv = sm[S_SCP + c * 16 + h] + sm[S_SCP + c * 16 + 8 + h];
                val = (sm[S_VCM + c] != 0.0f) ? NEGV : scv * 0.25f;
            }
            vv[idx] = val;
            mx = fmaxf(mx, val);
        }
#pragma unroll
        for (int off = 16; off; off >>= 1)
            mx = fmaxf(mx, __shfl_xor_sync(0xffffffffu, mx, off));
        float ssum = 0.f;
#pragma unroll
        for (int idx = 0; idx < 4; idx++) {
            int c = lane + 32 * idx;
            if (c < CC) {
                float e = expf(vv[idx] - mx);
                ssum += e;
                vv[idx] = e;
            }
        }
#pragma unroll
        for (int off = 16; off; off >>= 1)
            ssum += __shfl_xor_sync(0xffffffffu, ssum, off);
        float inv = 1.0f / ssum;
#pragma unroll
        for (int idx = 0; idx < 4; idx++) {
            int c = lane + 32 * idx;
            if (c < CC) sm[S_AT4 + c * 8 + h] = vv[idx] * inv;
        }
    }
    __syncthreads();

    // ===== P6: wsum[h][i] = sum_c attn[h][c]*cluster[c][i] (t<256) ===========
    if (t < 256) {
        int i = t & 127, par = t >> 7;
        float acc[4] = {0.f, 0.f, 0.f, 0.f};
#pragma unroll 4
        for (int c = 0; c < CC; c++) {
            float cv = sm[S_CS + c * 129 + i];
            float4 av = *(const float4*)(sm + S_AT4 + c * 8 + par * 4);
            acc[0] = fmaf(av.x, cv, acc[0]);
            acc[1] = fmaf(av.y, cv, acc[1]);
            acc[2] = fmaf(av.z, cv, acc[2]);
            acc[3] = fmaf(av.w, cv, acc[3]);
        }
        *(float4*)(sm + S_WS4 + i * 8 + par * 4) =
            make_float4(acc[0], acc[1], acc[2], acc[3]);
    }
    __syncthreads();

    // ===== P7: gv partials — warp w takes 8 rows of ZV =======================
    {
        const float* ZV = g_fold + 512 * DD;
        const int hsel = lane >> 2;
        float4 acc = make_float4(0.f, 0.f, 0.f, 0.f);
#pragma unroll
        for (int ii = 0; ii < 8; ii++) {
            int i = w * 8 + ii;
            float4 zv = *(const float4*)(ZV + (size_t)i * DD + c4);
            float s = sm[S_WS4 + i * 8 + hsel];
            acc.x = fmaf(s, zv.x, acc.x);
            acc.y = fmaf(s, zv.y, acc.y);
            acc.z = fmaf(s, zv.z, acc.z);
            acc.w = fmaf(s, zv.w, acc.w);
        }
        *(float4*)(sm + S_PB + w * 132 + c4) = acc;
    }
    __syncthreads();

    // ===== P8: gv reduce =====================================================
    if (t < DD) {
        float s = 0.f;
#pragma unroll
        for (int ww = 0; ww < 16; ww++) s += sm[S_PB + ww * 132 + t];
        sm[S_GV + t] = s;
    }
    __syncthreads();

    // ===== P9: gw partials — warp w takes 8 rows of ZW =======================
    {
        const float* ZW = g_fold + 640 * DD;
        float4 acc = make_float4(0.f, 0.f, 0.f, 0.f);
#pragma unroll
        for (int mm = 0; mm < 8; mm++) {
            int m = w * 8 + mm;
            float4 zw = *(const float4*)(ZW + (size_t)m * DD + c4);
            float s = sm[S_GV + m];
            acc.x = fmaf(s, zw.x, acc.x);
            acc.y = fmaf(s, zw.y, acc.y);
            acc.z = fmaf(s, zw.z, acc.z);
            acc.w = fmaf(s, zw.w, acc.w);
        }
        *(float4*)(sm + S_PB + w * 132 + c4) = acc;
    }
    __syncthreads();

    // ===== P10: gw reduce ====================================================
    if (t < DD) {
        float s = 0.f;
#pragma unroll
        for (int ww = 0; ww < 16; ww++) s += sm[S_PB + ww * 132 + t];
        sm[S_GW + t] = s;
    }
    __syncthreads();

    // ===== P11: logit partials (t<200) =======================================
    if (t < 2 * CC) {
        int c = t >> 1, half = t & 1;
        float acc = 0.f;
        int i0 = half * 64;
#pragma unroll 8
        for (int i = i0; i < i0 + 64; i++)
            acc = fmaf(sm[S_CS + c * 129 + i], sm[S_GW + i], acc);
        sm[S_PART + c * 2 + half] = acc;
    }
    __syncthreads();

    // ===== P12: finalize logits + argmax + lse (warp 0) ======================
    if (w == 0) {
        float vv[4];
        float bv = -INFINITY;
        int bi = 0x7fffffff;
#pragma unroll
        for (int idx = 0; idx < 4; idx++) {
            int c = lane + 32 * idx;
            float val = -INFINITY;
            if (c < CC) {
                float lg = (sm[S_PART + c * 2] + sm[S_PART + c * 2 + 1])
                           * 0.08838834764831845f;
                lg = tanhf(lg) * CLIPV;
                val = (sm[S_VCM + c] != 0.0f) ? NEGV : lg;
                sm[S_LGT + c] = val;
                if (val > bv || (val == bv && c < bi)) { bv = val; bi = c; }
            }
            vv[idx] = val;
        }
#pragma unroll
        for (int off = 16; off; off >>= 1) {
            float ov = __shfl_down_sync(0xffffffffu, bv, off);
            int oi = __shfl_down_sync(0xffffffffu, bi, off);
            if (ov > bv || (ov == bv && oi < bi)) { bv = ov; bi = oi; }
        }
        bv = __shfl_sync(0xffffffffu, bv, 0);
        bi = __shfl_sync(0xffffffffu, bi, 0);
        float s = 0.f;
#pragma unroll
        for (int idx = 0; idx < 4; idx++) {
            int c = lane + 32 * idx;
            if (c < CC) s += expf(vv[idx] - bv);
        }
#pragma unroll
        for (int off = 16; off; off >>= 1) s += __shfl_xor_sync(0xffffffffu, s, off);
        if (lane == 0) {
            sm[S_MISC + 0] = (float)bi;
            sm[S_MISC + 1] = bv + logf(s);
        }
    }
    __syncthreads();

    // ===== P13: outputs ======================================================
    const int gid = (int)sm[S_MISC + 0];
    const float mlse = sm[S_MISC + 1];
    float* aug = out + OUT_AUG + (size_t)b * 512;
    float* gout = out + OUT_GEMB + (size_t)b * 128;
    float* cpo = out + OUT_CLU + (size_t)b * CC;
    if (t < DD) {
        float ge = sm[S_CS + gid * 129 + t];
        aug[t]        = isnew ? sm[S_M2 + t] : 0.0f;
        aug[128 + t]  = isnew ? sm[S_CUR + t] : 0.0f;
        aug[256 + t]  = isnew ? ge : 0.0f;
        aug[384 + t]  = isnew ? sm[S_DEP + t] : 0.0f;
        gout[t]       = isnew ? ge : 0.0f;
    }
    if (t >= 256 && t < 256 + CC) {
        int c = t - 256;
        cpo[c] = isnew ? (sm[S_LGT + c] - mlse) : 0.0f;
    }
    if (t == 511) out[OUT_GUID + b] = isnew ? (float)gid : 0.0f;
}

extern "C" void kernel_launch(void* const* d_in, const int* in_sizes, int n_in,
                              void* d_out, int out_size) {
    (void)in_sizes; (void)n_in; (void)out_size;
    const float* depot   = (const float*)d_in[0];
    const float* cluster = (const float*)d_in[1];
    const float* curE    = (const float*)d_in[2];
    const float* node    = (const float*)d_in[3];
    const void*  isnewp  = d_in[4];
    const void*  cmaskp  = d_in[5];
    const void*  vcmp    = d_in[6];
    const void*  maskp   = d_in[7];
    const float* Wq  = (const float*)d_in[8];
    const float* Wk  = (const float*)d_in[9];
    const float* Wv  = (const float*)d_in[10];
    const float* Wks = (const float*)d_in[11];
    const float* Wmq = (const float*)d_in[12];
    const float* Wmk = (const float*)d_in[13];
    const float* Wmv = (const float*)d_in[14];
    const float* Wmo = (const float*)d_in[15];

    means_pre_kernel<<<PRE_CTAS + BB * SPLIT, 256>>>(
        node, maskp, cmaskp, Wq, Wk, Wv, Wks, Wmq, Wmk, Wmv, Wmo);

    cudaFuncSetAttribute(clu_fused_kernel,
                         cudaFuncAttributeMaxDynamicSharedMemorySize, SMEM_BYTES);
    clu_fused_kernel<<<BB, 512, SMEM_BYTES>>>(
        depot, cluster, curE, isnewp, vcmp, maskp, (float*)d_out);
}